// round 7
// baseline (speedup 1.0000x reference)
#include <cuda_runtime.h>
#include <cuda_bf16.h>
#include <mma.h>
#include <math.h>
#include <cstdint>

using namespace nvcuda;

// Problem constants
#define BATCH 8
#define NTOK  1024
#define DIM   1024
#define NHEAD 16
#define HDIM  64
#define QKV_COLS (3*NHEAD*HDIM)   // 3072
#define SCALE 0.125f              // 64^-0.5

// ---------------- scratch (device globals: no allocations allowed) -----------
__device__ float g_qkv [(size_t)BATCH*NTOK*QKV_COLS]; // rounded tf32 values
__device__ float g_O   [(size_t)BATCH*NTOK*DIM];
__device__ float g_xr  [(size_t)BATCH*NTOK*DIM];      // tf32-rounded x
__device__ float g_wqkvr[(size_t)DIM*QKV_COLS];       // tf32-rounded W_qkv
__device__ float g_wpr [(size_t)DIM*DIM];             // tf32-rounded W_proj
__device__ float g_regr[(size_t)NHEAD*NTOK*NTOK];     // tf32-rounded reg

// ---------------- cp.async helpers -------------------------------------------
__device__ __forceinline__ void cp_async16(float* smem, const float* gmem) {
    unsigned int s = (unsigned int)__cvta_generic_to_shared(smem);
    asm volatile("cp.async.cg.shared.global [%0], [%1], 16;\n" :: "r"(s), "l"(gmem));
}
__device__ __forceinline__ void cp_commit() {
    asm volatile("cp.async.commit_group;\n" ::: "memory");
}
template<int N>
__device__ __forceinline__ void cp_wait() {
    asm volatile("cp.async.wait_group %0;\n" :: "n"(N) : "memory");
}

// ---------------- elementwise tf32 rounding ----------------------------------
__global__ void round_tf32_kernel(const float* __restrict__ in,
                                  float* __restrict__ out, int n4)
{
    int i = blockIdx.x * blockDim.x + threadIdx.x;
    if (i < n4) {
        float4 v = reinterpret_cast<const float4*>(in)[i];
        v.x = wmma::__float_to_tf32(v.x);
        v.y = wmma::__float_to_tf32(v.y);
        v.z = wmma::__float_to_tf32(v.z);
        v.w = wmma::__float_to_tf32(v.w);
        reinterpret_cast<float4*>(out)[i] = v;
    }
}

// ---------------- pipelined tf32 GEMM: C[M,N] = A[M,K] @ B[K,N] ---------------
#define TILE_M 128
#define TILE_N 128
#define TILE_K 32
#define STAGES 3
#define A_LDS 40
#define B_LDS 136
#define GEMM_SMEM_BYTES (STAGES * (TILE_M*A_LDS + TILE_K*B_LDS) * 4)  // 113664

#define GEMM_COMPUTE_STAGE(sidx)                                                   \
    {                                                                              \
        const float* Asb = As + (size_t)(sidx) * TILE_M * A_LDS;                   \
        const float* Bsb = Bs + (size_t)(sidx) * TILE_K * B_LDS;                   \
        _Pragma("unroll")                                                          \
        for (int kk = 0; kk < TILE_K; kk += 8) {                                   \
            wmma::fragment<wmma::matrix_a,16,16,8,wmma::precision::tf32,wmma::row_major> af[2]; \
            wmma::fragment<wmma::matrix_b,16,16,8,wmma::precision::tf32,wmma::row_major> bf[4]; \
            _Pragma("unroll")                                                      \
            for (int i = 0; i < 2; i++)                                            \
                wmma::load_matrix_sync(af[i], Asb + (wm*32 + i*16)*A_LDS + kk, A_LDS); \
            _Pragma("unroll")                                                      \
            for (int j = 0; j < 4; j++)                                            \
                wmma::load_matrix_sync(bf[j], Bsb + kk*B_LDS + wn*64 + j*16, B_LDS); \
            _Pragma("unroll")                                                      \
            for (int i = 0; i < 2; i++)                                            \
                _Pragma("unroll")                                                  \
                for (int j = 0; j < 4; j++)                                        \
                    wmma::mma_sync(acc[i][j], af[i], bf[j], acc[i][j]);            \
        }                                                                          \
    }

template<bool ROUND_OUT>
__global__ void __launch_bounds__(256, 2)
gemm_tf32_pipe(const float* __restrict__ A,
               const float* __restrict__ B,
               float* __restrict__ C,
               int M, int N, int K)
{
    extern __shared__ float smp[];
    float* As = smp;
    float* Bs = smp + (size_t)STAGES * TILE_M * A_LDS;

    const int tid  = threadIdx.x;
    const int warp = tid >> 5;
    const int wm   = warp >> 1;
    const int wn   = warp & 1;
    const int row0 = blockIdx.y * TILE_M;
    const int col0 = blockIdx.x * TILE_N;

    const int ar = tid >> 3,  ac = (tid & 7)  << 2;
    const int br = tid >> 5,  bc = (tid & 31) << 2;

    wmma::fragment<wmma::accumulator,16,16,8,float> acc[2][4];
    #pragma unroll
    for (int i = 0; i < 2; i++)
        #pragma unroll
        for (int j = 0; j < 4; j++)
            wmma::fill_fragment(acc[i][j], 0.0f);

    const int KT = K / TILE_K;

    #pragma unroll
    for (int s = 0; s < STAGES-1; s++) {
        const float* Ab = A + (size_t)row0 * K + s * TILE_K;
        const float* Bb = B + (size_t)s * TILE_K * N + col0;
        float* Asd = As + (size_t)s * TILE_M * A_LDS;
        float* Bsd = Bs + (size_t)s * TILE_K * B_LDS;
        #pragma unroll
        for (int i = 0; i < 4; i++)
            cp_async16(Asd + (ar + i*32)*A_LDS + ac, Ab + (size_t)(ar + i*32)*K + ac);
        #pragma unroll
        for (int i = 0; i < 4; i++)
            cp_async16(Bsd + (br + i*8)*B_LDS + bc, Bb + (size_t)(br + i*8)*N + bc);
        cp_commit();
    }

    for (int kt = 0; kt < KT; kt++) {
        cp_wait<STAGES-2>();
        __syncthreads();
        int knext = kt + STAGES - 1;
        if (knext < KT) {
            int s = knext % STAGES;
            const float* Ab = A + (size_t)row0 * K + knext * TILE_K;
            const float* Bb = B + (size_t)knext * TILE_K * N + col0;
            float* Asd = As + (size_t)s * TILE_M * A_LDS;
            float* Bsd = Bs + (size_t)s * TILE_K * B_LDS;
            #pragma unroll
            for (int i = 0; i < 4; i++)
                cp_async16(Asd + (ar + i*32)*A_LDS + ac, Ab + (size_t)(ar + i*32)*K + ac);
            #pragma unroll
            for (int i = 0; i < 4; i++)
                cp_async16(Bsd + (br + i*8)*B_LDS + bc, Bb + (size_t)(br + i*8)*N + bc);
            cp_commit();
        }
        GEMM_COMPUTE_STAGE(kt % STAGES);
    }

    #pragma unroll
    for (int i = 0; i < 2; i++)
        #pragma unroll
        for (int j = 0; j < 4; j++) {
            if (ROUND_OUT) {
                #pragma unroll
                for (int t = 0; t < acc[i][j].num_elements; t++)
                    acc[i][j].x[t] = wmma::__float_to_tf32(acc[i][j].x[t]);
            }
            wmma::store_matrix_sync(&C[(size_t)(row0 + wm*32 + i*16) * N + col0 + wn*64 + j*16],
                                    acc[i][j], N, wmma::mem_row_major);
        }
}

// ---------------- reg @ V accumulated into g_O, pipelined ---------------------
__global__ void __launch_bounds__(256, 2)
regv_pipe(const float* __restrict__ reg,
          const float* __restrict__ qkv,
          float* __restrict__ O)
{
    extern __shared__ float smp[];
    float* As = smp;
    float* Bs = smp + (size_t)STAGES * TILE_M * A_LDS;

    const int h    = blockIdx.z;
    const int tid  = threadIdx.x;
    const int warp = tid >> 5;
    const int wm   = warp >> 1;
    const int wn   = warp & 1;
    const int row0 = blockIdx.y * TILE_M;
    const int col0 = blockIdx.x * TILE_N;

    const float* A = reg + (size_t)h * NTOK * NTOK;
    const int K = NTOK;

    const int ar = tid >> 3,  ac = (tid & 7)  << 2;
    const int br = tid >> 5,  bc = (tid & 31) << 2;
    const int jcol = col0 + bc;
    const int gb = jcol >> 6, gd = jcol & 63;
    const float* Vbase = qkv + (size_t)gb * (NTOK*QKV_COLS) + 2*NHEAD*HDIM + h*64 + gd;

    wmma::fragment<wmma::accumulator,16,16,8,float> acc[2][4];
    #pragma unroll
    for (int i = 0; i < 2; i++)
        #pragma unroll
        for (int j = 0; j < 4; j++) {
            int rowf = row0 + wm*32 + i*16;
            int colf = col0 + wn*64 + j*16;
            int b = colf >> 6, d = colf & 63;
            const float* p = O + (size_t)b * (NTOK*DIM) + (size_t)rowf * DIM + h*64 + d;
            wmma::load_matrix_sync(acc[i][j], p, DIM, wmma::mem_row_major);
        }

    const int KT = K / TILE_K;

    #pragma unroll
    for (int s = 0; s < STAGES-1; s++) {
        const float* Ab = A + (size_t)row0 * K + s * TILE_K;
        float* Asd = As + (size_t)s * TILE_M * A_LDS;
        float* Bsd = Bs + (size_t)s * TILE_K * B_LDS;
        #pragma unroll
        for (int i = 0; i < 4; i++)
            cp_async16(Asd + (ar + i*32)*A_LDS + ac, Ab + (size_t)(ar + i*32)*K + ac);
        #pragma unroll
        for (int i = 0; i < 4; i++)
            cp_async16(Bsd + (br + i*8)*B_LDS + bc,
                       Vbase + (size_t)(s*TILE_K + br + i*8) * QKV_COLS);
        cp_commit();
    }

    for (int kt = 0; kt < KT; kt++) {
        cp_wait<STAGES-2>();
        __syncthreads();
        int knext = kt + STAGES - 1;
        if (knext < KT) {
            int s = knext % STAGES;
            const float* Ab = A + (size_t)row0 * K + knext * TILE_K;
            float* Asd = As + (size_t)s * TILE_M * A_LDS;
            float* Bsd = Bs + (size_t)s * TILE_K * B_LDS;
            #pragma unroll
            for (int i = 0; i < 4; i++)
                cp_async16(Asd + (ar + i*32)*A_LDS + ac, Ab + (size_t)(ar + i*32)*K + ac);
            #pragma unroll
            for (int i = 0; i < 4; i++)
                cp_async16(Bsd + (br + i*8)*B_LDS + bc,
                           Vbase + (size_t)(knext*TILE_K + br + i*8) * QKV_COLS);
            cp_commit();
        }
        GEMM_COMPUTE_STAGE(kt % STAGES);
    }

    #pragma unroll
    for (int i = 0; i < 2; i++)
        #pragma unroll
        for (int j = 0; j < 4; j++) {
            int rowf = row0 + wm*32 + i*16;
            int colf = col0 + wn*64 + j*16;
            int b = colf >> 6, d = colf & 63;
            float* p = O + (size_t)b * (NTOK*DIM) + (size_t)rowf * DIM + h*64 + d;
            #pragma unroll
            for (int t = 0; t < acc[i][j].num_elements; t++)
                acc[i][j].x[t] = wmma::__float_to_tf32(acc[i][j].x[t]);
            wmma::store_matrix_sync(p, acc[i][j], DIM, wmma::mem_row_major);
        }
}

// ---------------- fused flash attention (softmax part), pipelined -------------
// KV chunks of 64 rows, double-buffered with cp.async. Q pre-scaled by SCALE
// (exact on tf32 values). smem (floats):
//   q_s [128][68] @0, k_s 2x[64][68] @8704, v_s 2x[64][68] @17408,
//   s_s [128][68] @26112, o_s [128][64] @34816 ; total 43008 f = 172032 B
#define FLASH_SMEM_BYTES 172032
#define KV_CHUNK 64
#define NCHUNK (NTOK / KV_CHUNK)   // 16
#define KVBUF (KV_CHUNK * 68)      // 4352 floats per buffer

__global__ void flash_kernel(const float* __restrict__ qkv, float* __restrict__ O)
{
    extern __shared__ float sm[];
    float* q_s = sm;
    float* k_s = sm + 8704;
    float* v_s = sm + 17408;
    float* s_s = sm + 26112;
    float* o_s = sm + 34816;

    const int qb   = blockIdx.x;
    const int h    = blockIdx.y;
    const int b    = blockIdx.z;
    const int tid  = threadIdx.x;
    const int warp = tid >> 5;
    const int lane = tid & 31;

    const size_t bhbase = (size_t)(b*NTOK) * QKV_COLS + h*64;

    // prologue: cp.async chunk 0 into buffer 0 (K and V: 1024 float4 each)
    {
        const float* kb = qkv + bhbase + NHEAD*HDIM;
        const float* vb = qkv + bhbase + 2*NHEAD*HDIM;
        #pragma unroll
        for (int i = 0; i < 4; i++) {
            int idx = tid + i * 256;                 // 0..1023
            int r = idx >> 4, c = (idx & 15) << 2;
            cp_async16(&k_s[r*68 + c], kb + (size_t)r * QKV_COLS + c);
            cp_async16(&v_s[r*68 + c], vb + (size_t)r * QKV_COLS + c);
        }
        cp_commit();
    }

    // load Q (scaled by SCALE) + zero O while chunk 0 is in flight
    const size_t qbase = bhbase + (size_t)(qb*128) * QKV_COLS;
    #pragma unroll
    for (int i = 0; i < 8; i++) {
        int idx = tid + i * 256;                     // 2048 float4
        int r = idx >> 4, c = (idx & 15) << 2;
        float4 v = *reinterpret_cast<const float4*>(&qkv[qbase + (size_t)r * QKV_COLS + c]);
        q_s[r*68 + c    ] = v.x * SCALE;
        q_s[r*68 + c + 1] = v.y * SCALE;
        q_s[r*68 + c + 2] = v.z * SCALE;
        q_s[r*68 + c + 3] = v.w * SCALE;
    }
    for (int i = tid; i < 128*64; i += 256) o_s[i] = 0.0f;

    const int srow = tid >> 1;                       // row owned (2 threads/row)
    const int half = tid & 1;
    float m_run = -1e30f, l_run = 0.0f;

    for (int j = 0; j < NCHUNK; j++) {
        cp_wait<0>();            // chunk j resident
        __syncthreads();         // (a) chunk j visible  (b) all warps done with buf (j+1)&1

        if (j + 1 < NCHUNK) {    // prefetch chunk j+1 into the other buffer
            const float* kb = qkv + bhbase + (size_t)((j+1)*KV_CHUNK) * QKV_COLS + NHEAD*HDIM;
            const float* vb = qkv + bhbase + (size_t)((j+1)*KV_CHUNK) * QKV_COLS + 2*NHEAD*HDIM;
            float* kd = k_s + ((j+1) & 1) * KVBUF;
            float* vd = v_s + ((j+1) & 1) * KVBUF;
            #pragma unroll
            for (int i = 0; i < 4; i++) {
                int idx = tid + i * 256;
                int r = idx >> 4, c = (idx & 15) << 2;
                cp_async16(&kd[r*68 + c], kb + (size_t)r * QKV_COLS + c);
                cp_async16(&vd[r*68 + c], vb + (size_t)r * QKV_COLS + c);
            }
            cp_commit();
        }

        const float* kcur = k_s + (j & 1) * KVBUF;
        const float* vcur = v_s + (j & 1) * KVBUF;

        // ---- S = Qs @ K^T : warp w -> 16 rows x 64 cols
        {
            wmma::fragment<wmma::accumulator,16,16,8,float> sacc[4];
            #pragma unroll
            for (int n = 0; n < 4; n++) wmma::fill_fragment(sacc[n], 0.0f);
            #pragma unroll
            for (int kk = 0; kk < 64; kk += 8) {
                wmma::fragment<wmma::matrix_a,16,16,8,wmma::precision::tf32,wmma::row_major> af;
                wmma::load_matrix_sync(af, &q_s[(warp*16)*68 + kk], 68);
                #pragma unroll
                for (int n = 0; n < 4; n++) {
                    wmma::fragment<wmma::matrix_b,16,16,8,wmma::precision::tf32,wmma::col_major> bf;
                    wmma::load_matrix_sync(bf, &kcur[(n*16)*68 + kk], 68);
                    wmma::mma_sync(sacc[n], af, bf, sacc[n]);
                }
            }
            #pragma unroll
            for (int n = 0; n < 4; n++)
                wmma::store_matrix_sync(&s_s[(warp*16)*68 + n*16], sacc[n], 68, wmma::mem_row_major);
        }
        __syncwarp();

        // ---- online softmax: 2 threads per row, 32 cols each
        {
            float* sp = &s_s[srow*68 + half*32];
            float mx = -1e30f;
            #pragma unroll
            for (int c = 0; c < 32; c++) mx = fmaxf(mx, sp[c]);
            mx = fmaxf(mx, __shfl_xor_sync(0xffffffffu, mx, 1));
            float m_new = fmaxf(m_run, mx);
            float corr  = __expf(m_run - m_new);
            float sum = 0.0f;
            #pragma unroll
            for (int c = 0; c < 32; c++) {
                float p = wmma::__float_to_tf32(__expf(sp[c] - m_new));
                sp[c] = p;
                sum += p;
            }
            sum += __shfl_xor_sync(0xffffffffu, sum, 1);
            l_run = l_run * corr + sum;
            m_run = m_new;
            float* op = &o_s[srow*64 + half*32];
            #pragma unroll
            for (int c = 0; c < 32; c++) op[c] *= corr;
        }
        __syncwarp();

        // ---- PV: own 16 rows of P[128x64] @ V[64x64]
        {
            wmma::fragment<wmma::accumulator,16,16,8,float> oacc[4];
            #pragma unroll
            for (int n = 0; n < 4; n++) wmma::fill_fragment(oacc[n], 0.0f);
            #pragma unroll
            for (int kk = 0; kk < 64; kk += 8) {
                wmma::fragment<wmma::matrix_a,16,16,8,wmma::precision::tf32,wmma::row_major> af;
                wmma::load_matrix_sync(af, &s_s[(warp*16)*68 + kk], 68);
                #pragma unroll
                for (int n = 0; n < 4; n++) {
                    wmma::fragment<wmma::matrix_b,16,16,8,wmma::precision::tf32,wmma::row_major> bf;
                    wmma::load_matrix_sync(bf, &vcur[kk*68 + n*16], 68);
                    wmma::mma_sync(oacc[n], af, bf, oacc[n]);
                }
            }
            // stash PV result over own rows of s_s (P reads for those rows done)
            #pragma unroll
            for (int n = 0; n < 4; n++)
                wmma::store_matrix_sync(&s_s[(warp*16)*68 + n*16], oacc[n], 68, wmma::mem_row_major);
        }
        __syncwarp();
        for (int i = lane; i < 16*64; i += 32) {
            int r = warp*16 + (i >> 6), c = i & 63;
            o_s[r*64 + c] += s_s[r*68 + c];
        }
        __syncwarp();
    }

    // epilogue
    float inv_l = 1.0f / l_run;
    const size_t obase = (size_t)(b*NTOK + qb*128 + srow) * DIM + h*64 + half*32;
    #pragma unroll
    for (int c = 0; c < 32; c += 4) {
        float4 v;
        v.x = o_s[srow*64 + half*32 + c    ] * inv_l;
        v.y = o_s[srow*64 + half*32 + c + 1] * inv_l;
        v.z = o_s[srow*64 + half*32 + c + 2] * inv_l;
        v.w = o_s[srow*64 + half*32 + c + 3] * inv_l;
        *reinterpret_cast<float4*>(&O[obase + c]) = v;
    }
}

// ---------------- bias add ----------------------------------------------------
__global__ void bias_add_kernel(float* __restrict__ out, const float* __restrict__ bias)
{
    int i = blockIdx.x * blockDim.x + threadIdx.x;
    const int n4 = (BATCH*NTOK*DIM) / 4;
    if (i < n4) {
        float4 o = reinterpret_cast<float4*>(out)[i];
        float4 bv = reinterpret_cast<const float4*>(bias)[i & 255];
        o.x += bv.x; o.y += bv.y; o.z += bv.z; o.w += bv.w;
        reinterpret_cast<float4*>(out)[i] = o;
    }
}

// ---------------- launcher ----------------------------------------------------
extern "C" void kernel_launch(void* const* d_in, const int* in_sizes, int n_in,
                              void* d_out, int out_size)
{
    const float* x      = (const float*)d_in[0];
    const float* W_qkv  = (const float*)d_in[1];
    const float* reg    = (const float*)d_in[2];
    const float* W_proj = (const float*)d_in[3];
    const float* b_proj = (const float*)d_in[4];
    float* out = (float*)d_out;

    float *qkv_ptr, *O_ptr, *xr, *wqkvr, *wpr, *regr;
    cudaGetSymbolAddress((void**)&qkv_ptr, g_qkv);
    cudaGetSymbolAddress((void**)&O_ptr,   g_O);
    cudaGetSymbolAddress((void**)&xr,      g_xr);
    cudaGetSymbolAddress((void**)&wqkvr,   g_wqkvr);
    cudaGetSymbolAddress((void**)&wpr,     g_wpr);
    cudaGetSymbolAddress((void**)&regr,    g_regr);

    cudaFuncSetAttribute(gemm_tf32_pipe<true>,  cudaFuncAttributeMaxDynamicSharedMemorySize, GEMM_SMEM_BYTES);
    cudaFuncSetAttribute(gemm_tf32_pipe<false>, cudaFuncAttributeMaxDynamicSharedMemorySize, GEMM_SMEM_BYTES);
    cudaFuncSetAttribute(regv_pipe,             cudaFuncAttributeMaxDynamicSharedMemorySize, GEMM_SMEM_BYTES);
    cudaFuncSetAttribute(flash_kernel,          cudaFuncAttributeMaxDynamicSharedMemorySize, FLASH_SMEM_BYTES);

    // 0) pre-round GEMM operands to tf32
    {
        int n4;
        n4 = (BATCH*NTOK*DIM)/4;      round_tf32_kernel<<<(n4+255)/256, 256>>>(x, xr, n4);
        n4 = (DIM*QKV_COLS)/4;        round_tf32_kernel<<<(n4+255)/256, 256>>>(W_qkv, wqkvr, n4);
        n4 = (DIM*DIM)/4;             round_tf32_kernel<<<(n4+255)/256, 256>>>(W_proj, wpr, n4);
    }

    // 1) QKV projection (output rounded so flash/regv skip conversions)
    {
        dim3 grid(QKV_COLS / TILE_N, (BATCH*NTOK) / TILE_M);
        gemm_tf32_pipe<true><<<grid, 256, GEMM_SMEM_BYTES>>>(xr, wqkvr, qkv_ptr,
                                                             BATCH*NTOK, QKV_COLS, DIM);
    }

    // 2) flash attention -> g_O  (+ reg rounding, independent)
    {
        int n4 = (NHEAD*NTOK*NTOK)/4;
        round_tf32_kernel<<<(n4+255)/256, 256>>>(reg, regr, n4);
        dim3 grid(NTOK / 128, NHEAD, BATCH);
        flash_kernel<<<grid, 256, FLASH_SMEM_BYTES>>>(qkv_ptr, O_ptr);
    }

    // 3) reg @ V accumulated into g_O (output rounded for proj)
    {
        dim3 grid((BATCH*HDIM) / TILE_N, NTOK / TILE_M, NHEAD);
        regv_pipe<<<grid, 256, GEMM_SMEM_BYTES>>>(regr, qkv_ptr, O_ptr);
    }

    // 4) output projection (final — unrounded fp32 out)
    {
        dim3 grid(DIM / TILE_N, (BATCH*NTOK) / TILE_M);
        gemm_tf32_pipe<false><<<grid, 256, GEMM_SMEM_BYTES>>>(O_ptr, wpr, out,
                                                              BATCH*NTOK, DIM, DIM);
    }

    // 5) + b_proj
    {
        int n4 = (BATCH*NTOK*DIM) / 4;
        bias_add_kernel<<<(n4 + 255) / 256, 256>>>(out, b_proj);
    }
}

// round 9
// speedup vs baseline: 1.1660x; 1.1660x over previous
#include <cuda_runtime.h>
#include <cuda_bf16.h>
#include <mma.h>
#include <math.h>
#include <cstdint>

using namespace nvcuda;

// Problem constants
#define BATCH 8
#define NTOK  1024
#define DIM   1024
#define NHEAD 16
#define HDIM  64
#define QKV_COLS (3*NHEAD*HDIM)   // 3072
#define SCALE 0.125f              // 64^-0.5

// ---------------- scratch (device globals: no allocations allowed) -----------
__device__ float g_qkv [(size_t)BATCH*NTOK*QKV_COLS];
__device__ float g_O   [(size_t)BATCH*NTOK*DIM];
__device__ float g_xr  [(size_t)BATCH*NTOK*DIM];
__device__ float g_wqkvr[(size_t)DIM*QKV_COLS];
__device__ float g_wpr [(size_t)DIM*DIM];
__device__ float g_regr[(size_t)NHEAD*NTOK*NTOK];

// ---------------- cp.async helpers -------------------------------------------
__device__ __forceinline__ void cp_async16(float* smem, const float* gmem) {
    unsigned int s = (unsigned int)__cvta_generic_to_shared(smem);
    asm volatile("cp.async.cg.shared.global [%0], [%1], 16;\n" :: "r"(s), "l"(gmem));
}
__device__ __forceinline__ void cp_commit() {
    asm volatile("cp.async.commit_group;\n" ::: "memory");
}
template<int N>
__device__ __forceinline__ void cp_wait() {
    asm volatile("cp.async.wait_group %0;\n" :: "n"(N) : "memory");
}

// ---------------- elementwise tf32 rounding ----------------------------------
__global__ void round_tf32_kernel(const float* __restrict__ in,
                                  float* __restrict__ out, int n4)
{
    int i = blockIdx.x * blockDim.x + threadIdx.x;
    if (i < n4) {
        float4 v = reinterpret_cast<const float4*>(in)[i];
        v.x = wmma::__float_to_tf32(v.x);
        v.y = wmma::__float_to_tf32(v.y);
        v.z = wmma::__float_to_tf32(v.z);
        v.w = wmma::__float_to_tf32(v.w);
        reinterpret_cast<float4*>(out)[i] = v;
    }
}

// ---------------- pipelined tf32 GEMM: C[M,N] = A[M,K] @ B[K,N] ---------------
#define TILE_M 128
#define TILE_N 128
#define TILE_K 32
#define STAGES 3
#define A_LDS 40
#define B_LDS 136
#define GEMM_SMEM_BYTES (STAGES * (TILE_M*A_LDS + TILE_K*B_LDS) * 4)  // 113664

#define GEMM_COMPUTE_STAGE(sidx)                                                   \
    {                                                                              \
        const float* Asb = As + (size_t)(sidx) * TILE_M * A_LDS;                   \
        const float* Bsb = Bs + (size_t)(sidx) * TILE_K * B_LDS;                   \
        _Pragma("unroll")                                                          \
        for (int kk = 0; kk < TILE_K; kk += 8) {                                   \
            wmma::fragment<wmma::matrix_a,16,16,8,wmma::precision::tf32,wmma::row_major> af[2]; \
            wmma::fragment<wmma::matrix_b,16,16,8,wmma::precision::tf32,wmma::row_major> bf[4]; \
            _Pragma("unroll")                                                      \
            for (int i = 0; i < 2; i++)                                            \
                wmma::load_matrix_sync(af[i], Asb + (wm*32 + i*16)*A_LDS + kk, A_LDS); \
            _Pragma("unroll")                                                      \
            for (int j = 0; j < 4; j++)                                            \
                wmma::load_matrix_sync(bf[j], Bsb + kk*B_LDS + wn*64 + j*16, B_LDS); \
            _Pragma("unroll")                                                      \
            for (int i = 0; i < 2; i++)                                            \
                _Pragma("unroll")                                                  \
                for (int j = 0; j < 4; j++)                                        \
                    wmma::mma_sync(acc[i][j], af[i], bf[j], acc[i][j]);            \
        }                                                                          \
    }

template<bool ROUND_OUT>
__global__ void __launch_bounds__(256, 2)
gemm_tf32_pipe(const float* __restrict__ A,
               const float* __restrict__ B,
               float* __restrict__ C,
               int M, int N, int K)
{
    extern __shared__ float smp[];
    float* As = smp;
    float* Bs = smp + (size_t)STAGES * TILE_M * A_LDS;

    const int tid  = threadIdx.x;
    const int warp = tid >> 5;
    const int wm   = warp >> 1;
    const int wn   = warp & 1;
    const int row0 = blockIdx.y * TILE_M;
    const int col0 = blockIdx.x * TILE_N;

    const int ar = tid >> 3,  ac = (tid & 7)  << 2;
    const int br = tid >> 5,  bc = (tid & 31) << 2;

    wmma::fragment<wmma::accumulator,16,16,8,float> acc[2][4];
    #pragma unroll
    for (int i = 0; i < 2; i++)
        #pragma unroll
        for (int j = 0; j < 4; j++)
            wmma::fill_fragment(acc[i][j], 0.0f);

    const int KT = K / TILE_K;

    #pragma unroll
    for (int s = 0; s < STAGES-1; s++) {
        const float* Ab = A + (size_t)row0 * K + s * TILE_K;
        const float* Bb = B + (size_t)s * TILE_K * N + col0;
        float* Asd = As + (size_t)s * TILE_M * A_LDS;
        float* Bsd = Bs + (size_t)s * TILE_K * B_LDS;
        #pragma unroll
        for (int i = 0; i < 4; i++)
            cp_async16(Asd + (ar + i*32)*A_LDS + ac, Ab + (size_t)(ar + i*32)*K + ac);
        #pragma unroll
        for (int i = 0; i < 4; i++)
            cp_async16(Bsd + (br + i*8)*B_LDS + bc, Bb + (size_t)(br + i*8)*N + bc);
        cp_commit();
    }

    for (int kt = 0; kt < KT; kt++) {
        cp_wait<STAGES-2>();
        __syncthreads();
        int knext = kt + STAGES - 1;
        if (knext < KT) {
            int s = knext % STAGES;
            const float* Ab = A + (size_t)row0 * K + knext * TILE_K;
            const float* Bb = B + (size_t)knext * TILE_K * N + col0;
            float* Asd = As + (size_t)s * TILE_M * A_LDS;
            float* Bsd = Bs + (size_t)s * TILE_K * B_LDS;
            #pragma unroll
            for (int i = 0; i < 4; i++)
                cp_async16(Asd + (ar + i*32)*A_LDS + ac, Ab + (size_t)(ar + i*32)*K + ac);
            #pragma unroll
            for (int i = 0; i < 4; i++)
                cp_async16(Bsd + (br + i*8)*B_LDS + bc, Bb + (size_t)(br + i*8)*N + bc);
            cp_commit();
        }
        GEMM_COMPUTE_STAGE(kt % STAGES);
    }

    #pragma unroll
    for (int i = 0; i < 2; i++)
        #pragma unroll
        for (int j = 0; j < 4; j++) {
            if (ROUND_OUT) {
                #pragma unroll
                for (int t = 0; t < acc[i][j].num_elements; t++)
                    acc[i][j].x[t] = wmma::__float_to_tf32(acc[i][j].x[t]);
            }
            wmma::store_matrix_sync(&C[(size_t)(row0 + wm*32 + i*16) * N + col0 + wn*64 + j*16],
                                    acc[i][j], N, wmma::mem_row_major);
        }
}

// ---------------- reg @ V accumulated into g_O, pipelined ---------------------
__global__ void __launch_bounds__(256, 2)
regv_pipe(const float* __restrict__ reg,
          const float* __restrict__ qkv,
          float* __restrict__ O)
{
    extern __shared__ float smp[];
    float* As = smp;
    float* Bs = smp + (size_t)STAGES * TILE_M * A_LDS;

    const int h    = blockIdx.z;
    const int tid  = threadIdx.x;
    const int warp = tid >> 5;
    const int wm   = warp >> 1;
    const int wn   = warp & 1;
    const int row0 = blockIdx.y * TILE_M;
    const int col0 = blockIdx.x * TILE_N;

    const float* A = reg + (size_t)h * NTOK * NTOK;
    const int K = NTOK;

    const int ar = tid >> 3,  ac = (tid & 7)  << 2;
    const int br = tid >> 5,  bc = (tid & 31) << 2;
    const int jcol = col0 + bc;
    const int gb = jcol >> 6, gd = jcol & 63;
    const float* Vbase = qkv + (size_t)gb * (NTOK*QKV_COLS) + 2*NHEAD*HDIM + h*64 + gd;

    wmma::fragment<wmma::accumulator,16,16,8,float> acc[2][4];
    #pragma unroll
    for (int i = 0; i < 2; i++)
        #pragma unroll
        for (int j = 0; j < 4; j++) {
            int rowf = row0 + wm*32 + i*16;
            int colf = col0 + wn*64 + j*16;
            int b = colf >> 6, d = colf & 63;
            const float* p = O + (size_t)b * (NTOK*DIM) + (size_t)rowf * DIM + h*64 + d;
            wmma::load_matrix_sync(acc[i][j], p, DIM, wmma::mem_row_major);
        }

    const int KT = K / TILE_K;

    #pragma unroll
    for (int s = 0; s < STAGES-1; s++) {
        const float* Abp = A + (size_t)row0 * K + s * TILE_K;
        float* Asd = As + (size_t)s * TILE_M * A_LDS;
        float* Bsd = Bs + (size_t)s * TILE_K * B_LDS;
        #pragma unroll
        for (int i = 0; i < 4; i++)
            cp_async16(Asd + (ar + i*32)*A_LDS + ac, Abp + (size_t)(ar + i*32)*K + ac);
        #pragma unroll
        for (int i = 0; i < 4; i++)
            cp_async16(Bsd + (br + i*8)*B_LDS + bc,
                       Vbase + (size_t)(s*TILE_K + br + i*8) * QKV_COLS);
        cp_commit();
    }

    for (int kt = 0; kt < KT; kt++) {
        cp_wait<STAGES-2>();
        __syncthreads();
        int knext = kt + STAGES - 1;
        if (knext < KT) {
            int s = knext % STAGES;
            const float* Abp = A + (size_t)row0 * K + knext * TILE_K;
            float* Asd = As + (size_t)s * TILE_M * A_LDS;
            float* Bsd = Bs + (size_t)s * TILE_K * B_LDS;
            #pragma unroll
            for (int i = 0; i < 4; i++)
                cp_async16(Asd + (ar + i*32)*A_LDS + ac, Abp + (size_t)(ar + i*32)*K + ac);
            #pragma unroll
            for (int i = 0; i < 4; i++)
                cp_async16(Bsd + (br + i*8)*B_LDS + bc,
                           Vbase + (size_t)(knext*TILE_K + br + i*8) * QKV_COLS);
            cp_commit();
        }
        GEMM_COMPUTE_STAGE(kt % STAGES);
    }

    #pragma unroll
    for (int i = 0; i < 2; i++)
        #pragma unroll
        for (int j = 0; j < 4; j++) {
            int rowf = row0 + wm*32 + i*16;
            int colf = col0 + wn*64 + j*16;
            int b = colf >> 6, d = colf & 63;
            float* p = O + (size_t)b * (NTOK*DIM) + (size_t)rowf * DIM + h*64 + d;
            #pragma unroll
            for (int t = 0; t < acc[i][j].num_elements; t++)
                acc[i][j].x[t] = wmma::__float_to_tf32(acc[i][j].x[t]);
            wmma::store_matrix_sync(p, acc[i][j], DIM, wmma::mem_row_major);
        }
}

// ---------------- fused flash attention, overlapped KV loads ------------------
// Chunk = 128 KV rows. K double-buffered, V single-buffered, cp.async with
// split waits. O accumulator in registers (thread owns half a row).
// smem (floats): q_s [128][68] @0, k_s 2x[128][68] @8704, v_s [128][68] @26112,
//                s_s [128][132] @34816 ; total 51712 floats = 206848 B
#define FLASH_SMEM_BYTES 206848
#define KBUF 8704

__global__ void __launch_bounds__(256, 1)
flash_kernel(const float* __restrict__ qkv, float* __restrict__ O)
{
    extern __shared__ float sm[];
    float* q_s = sm;
    float* k_s = sm + 8704;
    float* v_s = sm + 26112;
    float* s_s = sm + 34816;

    const int qb   = blockIdx.x;
    const int h    = blockIdx.y;
    const int b    = blockIdx.z;
    const int tid  = threadIdx.x;
    const int warp = tid >> 5;

    const size_t bhbase = (size_t)(b*NTOK) * QKV_COLS + h*64;

    // prologue: K_0 -> k buf 0 (group), V_0 -> v (group)
    {
        const float* kb = qkv + bhbase + NHEAD*HDIM;
        #pragma unroll
        for (int i = 0; i < 8; i++) {
            int idx = tid + i * 256;                 // 2048 float4
            int r = idx >> 4, c = (idx & 15) << 2;
            cp_async16(&k_s[r*68 + c], kb + (size_t)r * QKV_COLS + c);
        }
        cp_commit();
        const float* vb = qkv + bhbase + 2*NHEAD*HDIM;
        #pragma unroll
        for (int i = 0; i < 8; i++) {
            int idx = tid + i * 256;
            int r = idx >> 4, c = (idx & 15) << 2;
            cp_async16(&v_s[r*68 + c], vb + (size_t)r * QKV_COLS + c);
        }
        cp_commit();
    }

    // load Q (pre-scaled) while chunk 0 is in flight
    const size_t qbase = bhbase + (size_t)(qb*128) * QKV_COLS;
    #pragma unroll
    for (int i = 0; i < 8; i++) {
        int idx = tid + i * 256;
        int r = idx >> 4, c = (idx & 15) << 2;
        float4 v = *reinterpret_cast<const float4*>(&qkv[qbase + (size_t)r * QKV_COLS + c]);
        q_s[r*68 + c    ] = v.x * SCALE;
        q_s[r*68 + c + 1] = v.y * SCALE;
        q_s[r*68 + c + 2] = v.z * SCALE;
        q_s[r*68 + c + 3] = v.w * SCALE;
    }

    const int srow = tid >> 1;                      // owned row (2 threads/row)
    const int half = tid & 1;                       // which half of the row
    float o_reg[32];
    #pragma unroll
    for (int c = 0; c < 32; c++) o_reg[c] = 0.0f;
    float m_run = -1e30f, l_run = 0.0f;

    for (int j = 0; j < 8; j++) {
        // issue V_j (j>0; buffer freed by last iteration's trailing barrier)
        if (j > 0) {
            const float* vb = qkv + bhbase + (size_t)(j*128) * QKV_COLS + 2*NHEAD*HDIM;
            #pragma unroll
            for (int i = 0; i < 8; i++) {
                int idx = tid + i * 256;
                int r = idx >> 4, c = (idx & 15) << 2;
                cp_async16(&v_s[r*68 + c], vb + (size_t)r * QKV_COLS + c);
            }
            cp_commit();
        }
        // issue K_{j+1} into the other K buffer
        if (j < 7) {
            const float* kb = qkv + bhbase + (size_t)((j+1)*128) * QKV_COLS + NHEAD*HDIM;
            float* kd = k_s + ((j+1) & 1) * KBUF;
            #pragma unroll
            for (int i = 0; i < 8; i++) {
                int idx = tid + i * 256;
                int r = idx >> 4, c = (idx & 15) << 2;
                cp_async16(&kd[r*68 + c], kb + (size_t)r * QKV_COLS + c);
            }
            cp_commit();
        }

        // wait for K_j (pending after: V_j, K_{j+1} when present)
        if (j < 7) cp_wait<2>(); else cp_wait<1>();
        __syncthreads();

        const float* kcur = k_s + (j & 1) * KBUF;

        // ---- S = Qs @ K^T : warp w -> rows w*16..+16, 128 cols
        {
            wmma::fragment<wmma::accumulator,16,16,8,float> sacc[8];
            #pragma unroll
            for (int n = 0; n < 8; n++) wmma::fill_fragment(sacc[n], 0.0f);
            #pragma unroll
            for (int kk = 0; kk < 64; kk += 8) {
                wmma::fragment<wmma::matrix_a,16,16,8,wmma::precision::tf32,wmma::row_major> af;
                wmma::load_matrix_sync(af, &q_s[(warp*16)*68 + kk], 68);
                #pragma unroll
                for (int n = 0; n < 8; n++) {
                    wmma::fragment<wmma::matrix_b,16,16,8,wmma::precision::tf32,wmma::col_major> bf;
                    wmma::load_matrix_sync(bf, &kcur[(n*16)*68 + kk], 68);
                    wmma::mma_sync(sacc[n], af, bf, sacc[n]);
                }
            }
            #pragma unroll
            for (int n = 0; n < 8; n++)
                wmma::store_matrix_sync(&s_s[(warp*16)*132 + n*16], sacc[n], 132, wmma::mem_row_major);
        }
        __syncwarp();

        // ---- online softmax (warp-private rows; overlaps the V_j load)
        {
            float* sp = &s_s[srow*132 + half*64];
            float mx = -1e30f;
            #pragma unroll
            for (int c = 0; c < 64; c++) mx = fmaxf(mx, sp[c]);
            mx = fmaxf(mx, __shfl_xor_sync(0xffffffffu, mx, 1));
            float m_new = fmaxf(m_run, mx);
            float corr  = __expf(m_run - m_new);
            float sum = 0.0f;
            #pragma unroll
            for (int c = 0; c < 64; c++) {
                float p = wmma::__float_to_tf32(__expf(sp[c] - m_new));
                sp[c] = p;
                sum += p;
            }
            sum += __shfl_xor_sync(0xffffffffu, sum, 1);
            l_run = l_run * corr + sum;
            m_run = m_new;
            #pragma unroll
            for (int c = 0; c < 32; c++) o_reg[c] *= corr;
        }

        // wait for V_j (only K_{j+1} may remain pending)
        if (j < 7) cp_wait<1>(); else cp_wait<0>();
        __syncthreads();

        // ---- PV: own 16 rows of P[128x128] @ V[128x64] -> stash in s_s
        {
            wmma::fragment<wmma::accumulator,16,16,8,float> oacc[4];
            #pragma unroll
            for (int n = 0; n < 4; n++) wmma::fill_fragment(oacc[n], 0.0f);
            #pragma unroll
            for (int kk = 0; kk < 128; kk += 8) {
                wmma::fragment<wmma::matrix_a,16,16,8,wmma::precision::tf32,wmma::row_major> af;
                wmma::load_matrix_sync(af, &s_s[(warp*16)*132 + kk], 132);
                #pragma unroll
                for (int n = 0; n < 4; n++) {
                    wmma::fragment<wmma::matrix_b,16,16,8,wmma::precision::tf32,wmma::row_major> bf;
                    wmma::load_matrix_sync(bf, &v_s[kk*68 + n*16], 68);
                    wmma::mma_sync(oacc[n], af, bf, oacc[n]);
                }
            }
            #pragma unroll
            for (int n = 0; n < 4; n++)
                wmma::store_matrix_sync(&s_s[(warp*16)*132 + n*16], oacc[n], 132, wmma::mem_row_major);
        }
        __syncwarp();
        #pragma unroll
        for (int c = 0; c < 32; c++)
            o_reg[c] += s_s[srow*132 + half*32 + c];
        __syncthreads();   // all warps done with v_s/s_s before next iter's loads
    }

    // epilogue from registers
    float inv_l = 1.0f / l_run;
    float* op = O + (size_t)(b*NTOK + qb*128 + srow) * DIM + h*64 + half*32;
    #pragma unroll
    for (int c = 0; c < 32; c += 4) {
        float4 v;
        v.x = o_reg[c    ] * inv_l;
        v.y = o_reg[c + 1] * inv_l;
        v.z = o_reg[c + 2] * inv_l;
        v.w = o_reg[c + 3] * inv_l;
        *reinterpret_cast<float4*>(op + c) = v;
    }
}

// ---------------- bias add ----------------------------------------------------
__global__ void bias_add_kernel(float* __restrict__ out, const float* __restrict__ bias)
{
    int i = blockIdx.x * blockDim.x + threadIdx.x;
    const int n4 = (BATCH*NTOK*DIM) / 4;
    if (i < n4) {
        float4 o = reinterpret_cast<float4*>(out)[i];
        float4 bv = reinterpret_cast<const float4*>(bias)[i & 255];
        o.x += bv.x; o.y += bv.y; o.z += bv.z; o.w += bv.w;
        reinterpret_cast<float4*>(out)[i] = o;
    }
}

// ---------------- launcher ----------------------------------------------------
extern "C" void kernel_launch(void* const* d_in, const int* in_sizes, int n_in,
                              void* d_out, int out_size)
{
    const float* x      = (const float*)d_in[0];
    const float* W_qkv  = (const float*)d_in[1];
    const float* reg    = (const float*)d_in[2];
    const float* W_proj = (const float*)d_in[3];
    const float* b_proj = (const float*)d_in[4];
    float* out = (float*)d_out;

    float *qkv_ptr, *O_ptr, *xr, *wqkvr, *wpr, *regr;
    cudaGetSymbolAddress((void**)&qkv_ptr, g_qkv);
    cudaGetSymbolAddress((void**)&O_ptr,   g_O);
    cudaGetSymbolAddress((void**)&xr,      g_xr);
    cudaGetSymbolAddress((void**)&wqkvr,   g_wqkvr);
    cudaGetSymbolAddress((void**)&wpr,     g_wpr);
    cudaGetSymbolAddress((void**)&regr,    g_regr);

    cudaFuncSetAttribute(gemm_tf32_pipe<true>,  cudaFuncAttributeMaxDynamicSharedMemorySize, GEMM_SMEM_BYTES);
    cudaFuncSetAttribute(gemm_tf32_pipe<false>, cudaFuncAttributeMaxDynamicSharedMemorySize, GEMM_SMEM_BYTES);
    cudaFuncSetAttribute(regv_pipe,             cudaFuncAttributeMaxDynamicSharedMemorySize, GEMM_SMEM_BYTES);
    cudaFuncSetAttribute(flash_kernel,          cudaFuncAttributeMaxDynamicSharedMemorySize, FLASH_SMEM_BYTES);

    // 0) pre-round GEMM operands to tf32
    {
        int n4;
        n4 = (BATCH*NTOK*DIM)/4;      round_tf32_kernel<<<(n4+255)/256, 256>>>(x, xr, n4);
        n4 = (DIM*QKV_COLS)/4;        round_tf32_kernel<<<(n4+255)/256, 256>>>(W_qkv, wqkvr, n4);
        n4 = (DIM*DIM)/4;             round_tf32_kernel<<<(n4+255)/256, 256>>>(W_proj, wpr, n4);
    }

    // 1) QKV projection (output rounded so flash/regv skip conversions)
    {
        dim3 grid(QKV_COLS / TILE_N, (BATCH*NTOK) / TILE_M);
        gemm_tf32_pipe<true><<<grid, 256, GEMM_SMEM_BYTES>>>(xr, wqkvr, qkv_ptr,
                                                             BATCH*NTOK, QKV_COLS, DIM);
    }

    // 2) flash attention -> g_O  (+ reg rounding, independent)
    {
        int n4 = (NHEAD*NTOK*NTOK)/4;
        round_tf32_kernel<<<(n4+255)/256, 256>>>(reg, regr, n4);
        dim3 grid(NTOK / 128, NHEAD, BATCH);
        flash_kernel<<<grid, 256, FLASH_SMEM_BYTES>>>(qkv_ptr, O_ptr);
    }

    // 3) reg @ V accumulated into g_O (output rounded for proj)
    {
        dim3 grid((BATCH*HDIM) / TILE_N, NTOK / TILE_M, NHEAD);
        regv_pipe<<<grid, 256, GEMM_SMEM_BYTES>>>(regr, qkv_ptr, O_ptr);
    }

    // 4) output projection (final — unrounded fp32 out)
    {
        dim3 grid(DIM / TILE_N, (BATCH*NTOK) / TILE_M);
        gemm_tf32_pipe<false><<<grid, 256, GEMM_SMEM_BYTES>>>(O_ptr, wpr, out,
                                                              BATCH*NTOK, DIM, DIM);
    }

    // 5) + b_proj
    {
        int n4 = (BATCH*NTOK*DIM) / 4;
        bias_add_kernel<<<(n4 + 255) / 256, 256>>>(out, b_proj);
    }
}

// round 10
// speedup vs baseline: 1.1794x; 1.0115x over previous
#include <cuda_runtime.h>
#include <cuda_bf16.h>
#include <mma.h>
#include <math.h>
#include <cstdint>

using namespace nvcuda;

// Problem constants
#define BATCH 8
#define NTOK  1024
#define DIM   1024
#define NHEAD 16
#define HDIM  64
#define QKV_COLS (3*NHEAD*HDIM)   // 3072
#define SCALE 0.125f              // 64^-0.5

// ---------------- scratch (device globals: no allocations allowed) -----------
__device__ float g_qkv [(size_t)BATCH*NTOK*QKV_COLS];
__device__ float g_O   [(size_t)BATCH*NTOK*DIM];      // flash output
__device__ float g_O2  [(size_t)BATCH*NTOK*DIM];      // regv output
__device__ float g_xr  [(size_t)BATCH*NTOK*DIM];
__device__ float g_wqkvr[(size_t)DIM*QKV_COLS];
__device__ float g_wpr [(size_t)DIM*DIM];
__device__ float g_regr[(size_t)NHEAD*NTOK*NTOK];

// ---------------- cp.async helpers -------------------------------------------
__device__ __forceinline__ void cp_async16(float* smem, const float* gmem) {
    unsigned int s = (unsigned int)__cvta_generic_to_shared(smem);
    asm volatile("cp.async.cg.shared.global [%0], [%1], 16;\n" :: "r"(s), "l"(gmem));
}
__device__ __forceinline__ void cp_commit() {
    asm volatile("cp.async.commit_group;\n" ::: "memory");
}
template<int N>
__device__ __forceinline__ void cp_wait() {
    asm volatile("cp.async.wait_group %0;\n" :: "n"(N) : "memory");
}

// ---------------- elementwise tf32 rounding ----------------------------------
__global__ void round_tf32_kernel(const float* __restrict__ in,
                                  float* __restrict__ out, int n4)
{
    int i = blockIdx.x * blockDim.x + threadIdx.x;
    if (i < n4) {
        float4 v = reinterpret_cast<const float4*>(in)[i];
        v.x = wmma::__float_to_tf32(v.x);
        v.y = wmma::__float_to_tf32(v.y);
        v.z = wmma::__float_to_tf32(v.z);
        v.w = wmma::__float_to_tf32(v.w);
        reinterpret_cast<float4*>(out)[i] = v;
    }
}

// ---------------- merge: O = round_tf32(O + O2) --------------------------------
__global__ void merge_round_kernel(float* __restrict__ o,
                                   const float* __restrict__ o2, int n4)
{
    int i = blockIdx.x * blockDim.x + threadIdx.x;
    if (i < n4) {
        float4 a = reinterpret_cast<float4*>(o)[i];
        float4 b = reinterpret_cast<const float4*>(o2)[i];
        a.x = wmma::__float_to_tf32(a.x + b.x);
        a.y = wmma::__float_to_tf32(a.y + b.y);
        a.z = wmma::__float_to_tf32(a.z + b.z);
        a.w = wmma::__float_to_tf32(a.w + b.w);
        reinterpret_cast<float4*>(o)[i] = a;
    }
}

// ---------------- pipelined tf32 GEMM: C[M,N] = A[M,K] @ B[K,N] ---------------
#define TILE_M 128
#define TILE_N 128
#define TILE_K 32
#define STAGES 3
#define A_LDS 40
#define B_LDS 136
#define GEMM_SMEM_BYTES (STAGES * (TILE_M*A_LDS + TILE_K*B_LDS) * 4)  // 113664

#define GEMM_COMPUTE_STAGE(sidx)                                                   \
    {                                                                              \
        const float* Asb = As + (size_t)(sidx) * TILE_M * A_LDS;                   \
        const float* Bsb = Bs + (size_t)(sidx) * TILE_K * B_LDS;                   \
        _Pragma("unroll")                                                          \
        for (int kk = 0; kk < TILE_K; kk += 8) {                                   \
            wmma::fragment<wmma::matrix_a,16,16,8,wmma::precision::tf32,wmma::row_major> af[2]; \
            wmma::fragment<wmma::matrix_b,16,16,8,wmma::precision::tf32,wmma::row_major> bf[4]; \
            _Pragma("unroll")                                                      \
            for (int i = 0; i < 2; i++)                                            \
                wmma::load_matrix_sync(af[i], Asb + (wm*32 + i*16)*A_LDS + kk, A_LDS); \
            _Pragma("unroll")                                                      \
            for (int j = 0; j < 4; j++)                                            \
                wmma::load_matrix_sync(bf[j], Bsb + kk*B_LDS + wn*64 + j*16, B_LDS); \
            _Pragma("unroll")                                                      \
            for (int i = 0; i < 2; i++)                                            \
                _Pragma("unroll")                                                  \
                for (int j = 0; j < 4; j++)                                        \
                    wmma::mma_sync(acc[i][j], af[i], bf[j], acc[i][j]);            \
        }                                                                          \
    }

template<bool ROUND_OUT>
__global__ void __launch_bounds__(256, 2)
gemm_tf32_pipe(const float* __restrict__ A,
               const float* __restrict__ B,
               float* __restrict__ C,
               int M, int N, int K)
{
    extern __shared__ float smp[];
    float* As = smp;
    float* Bs = smp + (size_t)STAGES * TILE_M * A_LDS;

    const int tid  = threadIdx.x;
    const int warp = tid >> 5;
    const int wm   = warp >> 1;
    const int wn   = warp & 1;
    const int row0 = blockIdx.y * TILE_M;
    const int col0 = blockIdx.x * TILE_N;

    const int ar = tid >> 3,  ac = (tid & 7)  << 2;
    const int br = tid >> 5,  bc = (tid & 31) << 2;

    wmma::fragment<wmma::accumulator,16,16,8,float> acc[2][4];
    #pragma unroll
    for (int i = 0; i < 2; i++)
        #pragma unroll
        for (int j = 0; j < 4; j++)
            wmma::fill_fragment(acc[i][j], 0.0f);

    const int KT = K / TILE_K;

    #pragma unroll
    for (int s = 0; s < STAGES-1; s++) {
        const float* Ab = A + (size_t)row0 * K + s * TILE_K;
        const float* Bb = B + (size_t)s * TILE_K * N + col0;
        float* Asd = As + (size_t)s * TILE_M * A_LDS;
        float* Bsd = Bs + (size_t)s * TILE_K * B_LDS;
        #pragma unroll
        for (int i = 0; i < 4; i++)
            cp_async16(Asd + (ar + i*32)*A_LDS + ac, Ab + (size_t)(ar + i*32)*K + ac);
        #pragma unroll
        for (int i = 0; i < 4; i++)
            cp_async16(Bsd + (br + i*8)*B_LDS + bc, Bb + (size_t)(br + i*8)*N + bc);
        cp_commit();
    }

    for (int kt = 0; kt < KT; kt++) {
        cp_wait<STAGES-2>();
        __syncthreads();
        int knext = kt + STAGES - 1;
        if (knext < KT) {
            int s = knext % STAGES;
            const float* Ab = A + (size_t)row0 * K + knext * TILE_K;
            const float* Bb = B + (size_t)knext * TILE_K * N + col0;
            float* Asd = As + (size_t)s * TILE_M * A_LDS;
            float* Bsd = Bs + (size_t)s * TILE_K * B_LDS;
            #pragma unroll
            for (int i = 0; i < 4; i++)
                cp_async16(Asd + (ar + i*32)*A_LDS + ac, Ab + (size_t)(ar + i*32)*K + ac);
            #pragma unroll
            for (int i = 0; i < 4; i++)
                cp_async16(Bsd + (br + i*8)*B_LDS + bc, Bb + (size_t)(br + i*8)*N + bc);
            cp_commit();
        }
        GEMM_COMPUTE_STAGE(kt % STAGES);
    }

    #pragma unroll
    for (int i = 0; i < 2; i++)
        #pragma unroll
        for (int j = 0; j < 4; j++) {
            if (ROUND_OUT) {
                #pragma unroll
                for (int t = 0; t < acc[i][j].num_elements; t++)
                    acc[i][j].x[t] = wmma::__float_to_tf32(acc[i][j].x[t]);
            }
            wmma::store_matrix_sync(&C[(size_t)(row0 + wm*32 + i*16) * N + col0 + wn*64 + j*16],
                                    acc[i][j], N, wmma::mem_row_major);
        }
}

// ---------------- reg @ V -> g_O2 (from zero), pipelined -----------------------
__global__ void __launch_bounds__(256, 2)
regv_pipe(const float* __restrict__ reg,
          const float* __restrict__ qkv,
          float* __restrict__ O2)
{
    extern __shared__ float smp[];
    float* As = smp;
    float* Bs = smp + (size_t)STAGES * TILE_M * A_LDS;

    const int h    = blockIdx.z;
    const int tid  = threadIdx.x;
    const int warp = tid >> 5;
    const int wm   = warp >> 1;
    const int wn   = warp & 1;
    const int row0 = blockIdx.y * TILE_M;
    const int col0 = blockIdx.x * TILE_N;

    const float* A = reg + (size_t)h * NTOK * NTOK;
    const int K = NTOK;

    const int ar = tid >> 3,  ac = (tid & 7)  << 2;
    const int br = tid >> 5,  bc = (tid & 31) << 2;
    const int jcol = col0 + bc;
    const int gb = jcol >> 6, gd = jcol & 63;
    const float* Vbase = qkv + (size_t)gb * (NTOK*QKV_COLS) + 2*NHEAD*HDIM + h*64 + gd;

    wmma::fragment<wmma::accumulator,16,16,8,float> acc[2][4];
    #pragma unroll
    for (int i = 0; i < 2; i++)
        #pragma unroll
        for (int j = 0; j < 4; j++)
            wmma::fill_fragment(acc[i][j], 0.0f);

    const int KT = K / TILE_K;

    #pragma unroll
    for (int s = 0; s < STAGES-1; s++) {
        const float* Abp = A + (size_t)row0 * K + s * TILE_K;
        float* Asd = As + (size_t)s * TILE_M * A_LDS;
        float* Bsd = Bs + (size_t)s * TILE_K * B_LDS;
        #pragma unroll
        for (int i = 0; i < 4; i++)
            cp_async16(Asd + (ar + i*32)*A_LDS + ac, Abp + (size_t)(ar + i*32)*K + ac);
        #pragma unroll
        for (int i = 0; i < 4; i++)
            cp_async16(Bsd + (br + i*8)*B_LDS + bc,
                       Vbase + (size_t)(s*TILE_K + br + i*8) * QKV_COLS);
        cp_commit();
    }

    for (int kt = 0; kt < KT; kt++) {
        cp_wait<STAGES-2>();
        __syncthreads();
        int knext = kt + STAGES - 1;
        if (knext < KT) {
            int s = knext % STAGES;
            const float* Abp = A + (size_t)row0 * K + knext * TILE_K;
            float* Asd = As + (size_t)s * TILE_M * A_LDS;
            float* Bsd = Bs + (size_t)s * TILE_K * B_LDS;
            #pragma unroll
            for (int i = 0; i < 4; i++)
                cp_async16(Asd + (ar + i*32)*A_LDS + ac, Abp + (size_t)(ar + i*32)*K + ac);
            #pragma unroll
            for (int i = 0; i < 4; i++)
                cp_async16(Bsd + (br + i*8)*B_LDS + bc,
                           Vbase + (size_t)(knext*TILE_K + br + i*8) * QKV_COLS);
            cp_commit();
        }
        GEMM_COMPUTE_STAGE(kt % STAGES);
    }

    #pragma unroll
    for (int i = 0; i < 2; i++)
        #pragma unroll
        for (int j = 0; j < 4; j++) {
            int rowf = row0 + wm*32 + i*16;
            int colf = col0 + wn*64 + j*16;
            int b = colf >> 6, d = colf & 63;
            float* p = O2 + (size_t)b * (NTOK*DIM) + (size_t)rowf * DIM + h*64 + d;
            wmma::store_matrix_sync(p, acc[i][j], DIM, wmma::mem_row_major);
        }
}

// ---------------- fused flash attention, overlapped KV loads ------------------
#define FLASH_SMEM_BYTES 206848
#define KBUF 8704

__global__ void __launch_bounds__(256, 1)
flash_kernel(const float* __restrict__ qkv, float* __restrict__ O)
{
    extern __shared__ float sm[];
    float* q_s = sm;
    float* k_s = sm + 8704;
    float* v_s = sm + 26112;
    float* s_s = sm + 34816;

    const int qb   = blockIdx.x;
    const int h    = blockIdx.y;
    const int b    = blockIdx.z;
    const int tid  = threadIdx.x;
    const int warp = tid >> 5;

    const size_t bhbase = (size_t)(b*NTOK) * QKV_COLS + h*64;

    {
        const float* kb = qkv + bhbase + NHEAD*HDIM;
        #pragma unroll
        for (int i = 0; i < 8; i++) {
            int idx = tid + i * 256;
            int r = idx >> 4, c = (idx & 15) << 2;
            cp_async16(&k_s[r*68 + c], kb + (size_t)r * QKV_COLS + c);
        }
        cp_commit();
        const float* vb = qkv + bhbase + 2*NHEAD*HDIM;
        #pragma unroll
        for (int i = 0; i < 8; i++) {
            int idx = tid + i * 256;
            int r = idx >> 4, c = (idx & 15) << 2;
            cp_async16(&v_s[r*68 + c], vb + (size_t)r * QKV_COLS + c);
        }
        cp_commit();
    }

    const size_t qbase = bhbase + (size_t)(qb*128) * QKV_COLS;
    #pragma unroll
    for (int i = 0; i < 8; i++) {
        int idx = tid + i * 256;
        int r = idx >> 4, c = (idx & 15) << 2;
        float4 v = *reinterpret_cast<const float4*>(&qkv[qbase + (size_t)r * QKV_COLS + c]);
        q_s[r*68 + c    ] = v.x * SCALE;
        q_s[r*68 + c + 1] = v.y * SCALE;
        q_s[r*68 + c + 2] = v.z * SCALE;
        q_s[r*68 + c + 3] = v.w * SCALE;
    }

    const int srow = tid >> 1;
    const int half = tid & 1;
    float o_reg[32];
    #pragma unroll
    for (int c = 0; c < 32; c++) o_reg[c] = 0.0f;
    float m_run = -1e30f, l_run = 0.0f;

    for (int j = 0; j < 8; j++) {
        if (j > 0) {
            const float* vb = qkv + bhbase + (size_t)(j*128) * QKV_COLS + 2*NHEAD*HDIM;
            #pragma unroll
            for (int i = 0; i < 8; i++) {
                int idx = tid + i * 256;
                int r = idx >> 4, c = (idx & 15) << 2;
                cp_async16(&v_s[r*68 + c], vb + (size_t)r * QKV_COLS + c);
            }
            cp_commit();
        }
        if (j < 7) {
            const float* kb = qkv + bhbase + (size_t)((j+1)*128) * QKV_COLS + NHEAD*HDIM;
            float* kd = k_s + ((j+1) & 1) * KBUF;
            #pragma unroll
            for (int i = 0; i < 8; i++) {
                int idx = tid + i * 256;
                int r = idx >> 4, c = (idx & 15) << 2;
                cp_async16(&kd[r*68 + c], kb + (size_t)r * QKV_COLS + c);
            }
            cp_commit();
        }

        if (j < 7) cp_wait<2>(); else cp_wait<1>();
        __syncthreads();

        const float* kcur = k_s + (j & 1) * KBUF;

        {
            wmma::fragment<wmma::accumulator,16,16,8,float> sacc[8];
            #pragma unroll
            for (int n = 0; n < 8; n++) wmma::fill_fragment(sacc[n], 0.0f);
            #pragma unroll
            for (int kk = 0; kk < 64; kk += 8) {
                wmma::fragment<wmma::matrix_a,16,16,8,wmma::precision::tf32,wmma::row_major> af;
                wmma::load_matrix_sync(af, &q_s[(warp*16)*68 + kk], 68);
                #pragma unroll
                for (int n = 0; n < 8; n++) {
                    wmma::fragment<wmma::matrix_b,16,16,8,wmma::precision::tf32,wmma::col_major> bf;
                    wmma::load_matrix_sync(bf, &kcur[(n*16)*68 + kk], 68);
                    wmma::mma_sync(sacc[n], af, bf, sacc[n]);
                }
            }
            #pragma unroll
            for (int n = 0; n < 8; n++)
                wmma::store_matrix_sync(&s_s[(warp*16)*132 + n*16], sacc[n], 132, wmma::mem_row_major);
        }
        __syncwarp();

        {
            float* sp = &s_s[srow*132 + half*64];
            float mx = -1e30f;
            #pragma unroll
            for (int c = 0; c < 64; c++) mx = fmaxf(mx, sp[c]);
            mx = fmaxf(mx, __shfl_xor_sync(0xffffffffu, mx, 1));
            float m_new = fmaxf(m_run, mx);
            float corr  = __expf(m_run - m_new);
            float sum = 0.0f;
            #pragma unroll
            for (int c = 0; c < 64; c++) {
                float p = wmma::__float_to_tf32(__expf(sp[c] - m_new));
                sp[c] = p;
                sum += p;
            }
            sum += __shfl_xor_sync(0xffffffffu, sum, 1);
            l_run = l_run * corr + sum;
            m_run = m_new;
            #pragma unroll
            for (int c = 0; c < 32; c++) o_reg[c] *= corr;
        }

        if (j < 7) cp_wait<1>(); else cp_wait<0>();
        __syncthreads();

        {
            wmma::fragment<wmma::accumulator,16,16,8,float> oacc[4];
            #pragma unroll
            for (int n = 0; n < 4; n++) wmma::fill_fragment(oacc[n], 0.0f);
            #pragma unroll
            for (int kk = 0; kk < 128; kk += 8) {
                wmma::fragment<wmma::matrix_a,16,16,8,wmma::precision::tf32,wmma::row_major> af;
                wmma::load_matrix_sync(af, &s_s[(warp*16)*132 + kk], 132);
                #pragma unroll
                for (int n = 0; n < 4; n++) {
                    wmma::fragment<wmma::matrix_b,16,16,8,wmma::precision::tf32,wmma::row_major> bf;
                    wmma::load_matrix_sync(bf, &v_s[kk*68 + n*16], 68);
                    wmma::mma_sync(oacc[n], af, bf, oacc[n]);
                }
            }
            #pragma unroll
            for (int n = 0; n < 4; n++)
                wmma::store_matrix_sync(&s_s[(warp*16)*132 + n*16], oacc[n], 132, wmma::mem_row_major);
        }
        __syncwarp();
        #pragma unroll
        for (int c = 0; c < 32; c++)
            o_reg[c] += s_s[srow*132 + half*32 + c];
        __syncthreads();
    }

    float inv_l = 1.0f / l_run;
    float* op = O + (size_t)(b*NTOK + qb*128 + srow) * DIM + h*64 + half*32;
    #pragma unroll
    for (int c = 0; c < 32; c += 4) {
        float4 v;
        v.x = o_reg[c    ] * inv_l;
        v.y = o_reg[c + 1] * inv_l;
        v.z = o_reg[c + 2] * inv_l;
        v.w = o_reg[c + 3] * inv_l;
        *reinterpret_cast<float4*>(op + c) = v;
    }
}

// ---------------- bias add ----------------------------------------------------
__global__ void bias_add_kernel(float* __restrict__ out, const float* __restrict__ bias)
{
    int i = blockIdx.x * blockDim.x + threadIdx.x;
    const int n4 = (BATCH*NTOK*DIM) / 4;
    if (i < n4) {
        float4 o = reinterpret_cast<float4*>(out)[i];
        float4 bv = reinterpret_cast<const float4*>(bias)[i & 255];
        o.x += bv.x; o.y += bv.y; o.z += bv.z; o.w += bv.w;
        reinterpret_cast<float4*>(out)[i] = o;
    }
}

// ---------------- launcher ----------------------------------------------------
extern "C" void kernel_launch(void* const* d_in, const int* in_sizes, int n_in,
                              void* d_out, int out_size)
{
    const float* x      = (const float*)d_in[0];
    const float* W_qkv  = (const float*)d_in[1];
    const float* reg    = (const float*)d_in[2];
    const float* W_proj = (const float*)d_in[3];
    const float* b_proj = (const float*)d_in[4];
    float* out = (float*)d_out;

    float *qkv_ptr, *O_ptr, *O2_ptr, *xr, *wqkvr, *wpr, *regr;
    cudaGetSymbolAddress((void**)&qkv_ptr, g_qkv);
    cudaGetSymbolAddress((void**)&O_ptr,   g_O);
    cudaGetSymbolAddress((void**)&O2_ptr,  g_O2);
    cudaGetSymbolAddress((void**)&xr,      g_xr);
    cudaGetSymbolAddress((void**)&wqkvr,   g_wqkvr);
    cudaGetSymbolAddress((void**)&wpr,     g_wpr);
    cudaGetSymbolAddress((void**)&regr,    g_regr);

    cudaFuncSetAttribute(gemm_tf32_pipe<true>,  cudaFuncAttributeMaxDynamicSharedMemorySize, GEMM_SMEM_BYTES);
    cudaFuncSetAttribute(gemm_tf32_pipe<false>, cudaFuncAttributeMaxDynamicSharedMemorySize, GEMM_SMEM_BYTES);
    cudaFuncSetAttribute(regv_pipe,             cudaFuncAttributeMaxDynamicSharedMemorySize, GEMM_SMEM_BYTES);
    cudaFuncSetAttribute(flash_kernel,          cudaFuncAttributeMaxDynamicSharedMemorySize, FLASH_SMEM_BYTES);

    // side stream + fork/join events (created once; reused — work per call identical)
    static cudaStream_t s2 = nullptr;
    static cudaEvent_t evFork = nullptr, evQKV = nullptr, evRegv = nullptr;
    if (!s2) {
        cudaStreamCreateWithFlags(&s2, cudaStreamNonBlocking);
        cudaEventCreateWithFlags(&evFork, cudaEventDisableTiming);
        cudaEventCreateWithFlags(&evQKV,  cudaEventDisableTiming);
        cudaEventCreateWithFlags(&evRegv, cudaEventDisableTiming);
    }

    // ---- main: round x, W_qkv (QKV deps) ----
    {
        int n4;
        n4 = (BATCH*NTOK*DIM)/4;  round_tf32_kernel<<<(n4+255)/256, 256>>>(x, xr, n4);
        n4 = (DIM*QKV_COLS)/4;    round_tf32_kernel<<<(n4+255)/256, 256>>>(W_qkv, wqkvr, n4);
    }
    cudaEventRecord(evFork, 0);

    // ---- side: round W_proj + reg (overlaps QKV GEMM) ----
    cudaStreamWaitEvent(s2, evFork, 0);
    {
        int n4;
        n4 = (DIM*DIM)/4;          round_tf32_kernel<<<(n4+255)/256, 256, 0, s2>>>(W_proj, wpr, n4);
        n4 = (NHEAD*NTOK*NTOK)/4;  round_tf32_kernel<<<(n4+255)/256, 256, 0, s2>>>(reg, regr, n4);
    }

    // ---- main: QKV projection ----
    {
        dim3 grid(QKV_COLS / TILE_N, (BATCH*NTOK) / TILE_M);
        gemm_tf32_pipe<true><<<grid, 256, GEMM_SMEM_BYTES>>>(xr, wqkvr, qkv_ptr,
                                                             BATCH*NTOK, QKV_COLS, DIM);
    }
    cudaEventRecord(evQKV, 0);

    // ---- side: regv (needs qkv + regr) — overlaps flash on main ----
    cudaStreamWaitEvent(s2, evQKV, 0);
    {
        dim3 grid((BATCH*HDIM) / TILE_N, NTOK / TILE_M, NHEAD);
        regv_pipe<<<grid, 256, GEMM_SMEM_BYTES, s2>>>(regr, qkv_ptr, O2_ptr);
    }
    cudaEventRecord(evRegv, s2);

    // ---- main: flash attention -> g_O ----
    {
        dim3 grid(NTOK / 128, NHEAD, BATCH);
        flash_kernel<<<grid, 256, FLASH_SMEM_BYTES>>>(qkv_ptr, O_ptr);
    }

    // ---- join: merge O += O2 (rounded), then proj ----
    cudaStreamWaitEvent(0, evRegv, 0);
    {
        int n4 = (BATCH*NTOK*DIM)/4;
        merge_round_kernel<<<(n4+255)/256, 256>>>(O_ptr, O2_ptr, n4);
    }
    {
        dim3 grid(DIM / TILE_N, (BATCH*NTOK) / TILE_M);
        gemm_tf32_pipe<false><<<grid, 256, GEMM_SMEM_BYTES>>>(O_ptr, wpr, out,
                                                              BATCH*NTOK, DIM, DIM);
    }
    {
        int n4 = (BATCH*NTOK*DIM) / 4;
        bias_add_kernel<<<(n4 + 255) / 256, 256>>>(out, b_proj);
    }
}

// round 11
// speedup vs baseline: 1.2221x; 1.0361x over previous
#include <cuda_runtime.h>
#include <cuda_bf16.h>
#include <mma.h>
#include <math.h>
#include <cstdint>

using namespace nvcuda;

// Problem constants
#define BATCH 8
#define NTOK  1024
#define DIM   1024
#define NHEAD 16
#define HDIM  64
#define QKV_COLS (3*NHEAD*HDIM)   // 3072
#define SCALE 0.125f              // 64^-0.5

// ---------------- scratch (device globals: no allocations allowed) -----------
__device__ float g_qkv [(size_t)BATCH*NTOK*QKV_COLS];
__device__ float g_O   [(size_t)BATCH*NTOK*DIM];      // flash output
__device__ float g_O2  [(size_t)BATCH*NTOK*DIM];      // regv output
__device__ float g_xr  [(size_t)BATCH*NTOK*DIM];
__device__ float g_wqkvr[(size_t)DIM*QKV_COLS];
__device__ float g_wpr [(size_t)DIM*DIM];
__device__ float g_regr[(size_t)NHEAD*NTOK*NTOK];

// ---------------- cp.async helpers -------------------------------------------
__device__ __forceinline__ void cp_async16(float* smem, const float* gmem) {
    unsigned int s = (unsigned int)__cvta_generic_to_shared(smem);
    asm volatile("cp.async.cg.shared.global [%0], [%1], 16;\n" :: "r"(s), "l"(gmem));
}
__device__ __forceinline__ void cp_commit() {
    asm volatile("cp.async.commit_group;\n" ::: "memory");
}
template<int N>
__device__ __forceinline__ void cp_wait() {
    asm volatile("cp.async.wait_group %0;\n" :: "n"(N) : "memory");
}

// ---------------- elementwise tf32 rounding ----------------------------------
__global__ void round_tf32_kernel(const float* __restrict__ in,
                                  float* __restrict__ out, int n4)
{
    int i = blockIdx.x * blockDim.x + threadIdx.x;
    if (i < n4) {
        float4 v = reinterpret_cast<const float4*>(in)[i];
        v.x = wmma::__float_to_tf32(v.x);
        v.y = wmma::__float_to_tf32(v.y);
        v.z = wmma::__float_to_tf32(v.z);
        v.w = wmma::__float_to_tf32(v.w);
        reinterpret_cast<float4*>(out)[i] = v;
    }
}

// ---------------- merge: O = round_tf32(O + O2) --------------------------------
__global__ void merge_round_kernel(float* __restrict__ o,
                                   const float* __restrict__ o2, int n4)
{
    int i = blockIdx.x * blockDim.x + threadIdx.x;
    if (i < n4) {
        float4 a = reinterpret_cast<float4*>(o)[i];
        float4 b = reinterpret_cast<const float4*>(o2)[i];
        a.x = wmma::__float_to_tf32(a.x + b.x);
        a.y = wmma::__float_to_tf32(a.y + b.y);
        a.z = wmma::__float_to_tf32(a.z + b.z);
        a.w = wmma::__float_to_tf32(a.w + b.w);
        reinterpret_cast<float4*>(o)[i] = a;
    }
}

// ---------------- pipelined tf32 GEMM: C[M,N] = A[M,K] @ B[K,N] ---------------
#define TILE_M 128
#define TILE_N 128
#define TILE_K 32
#define STAGES 3
#define A_LDS 40
#define B_LDS 136
#define GEMM_SMEM_BYTES (STAGES * (TILE_M*A_LDS + TILE_K*B_LDS) * 4)  // 113664

#define GEMM_COMPUTE_STAGE(sidx)                                                   \
    {                                                                              \
        const float* Asb = As + (size_t)(sidx) * TILE_M * A_LDS;                   \
        const float* Bsb = Bs + (size_t)(sidx) * TILE_K * B_LDS;                   \
        _Pragma("unroll")                                                          \
        for (int kk = 0; kk < TILE_K; kk += 8) {                                   \
            wmma::fragment<wmma::matrix_a,16,16,8,wmma::precision::tf32,wmma::row_major> af[2]; \
            wmma::fragment<wmma::matrix_b,16,16,8,wmma::precision::tf32,wmma::row_major> bf[4]; \
            _Pragma("unroll")                                                      \
            for (int i = 0; i < 2; i++)                                            \
                wmma::load_matrix_sync(af[i], Asb + (wm*32 + i*16)*A_LDS + kk, A_LDS); \
            _Pragma("unroll")                                                      \
            for (int j = 0; j < 4; j++)                                            \
                wmma::load_matrix_sync(bf[j], Bsb + kk*B_LDS + wn*64 + j*16, B_LDS); \
            _Pragma("unroll")                                                      \
            for (int i = 0; i < 2; i++)                                            \
                _Pragma("unroll")                                                  \
                for (int j = 0; j < 4; j++)                                        \
                    wmma::mma_sync(acc[i][j], af[i], bf[j], acc[i][j]);            \
        }                                                                          \
    }

template<bool ROUND_OUT>
__global__ void __launch_bounds__(256, 2)
gemm_tf32_pipe(const float* __restrict__ A,
               const float* __restrict__ B,
               float* __restrict__ C,
               int M, int N, int K)
{
    extern __shared__ float smp[];
    float* As = smp;
    float* Bs = smp + (size_t)STAGES * TILE_M * A_LDS;

    const int tid  = threadIdx.x;
    const int warp = tid >> 5;
    const int wm   = warp >> 1;
    const int wn   = warp & 1;
    const int row0 = blockIdx.y * TILE_M;
    const int col0 = blockIdx.x * TILE_N;

    const int ar = tid >> 3,  ac = (tid & 7)  << 2;
    const int br = tid >> 5,  bc = (tid & 31) << 2;

    wmma::fragment<wmma::accumulator,16,16,8,float> acc[2][4];
    #pragma unroll
    for (int i = 0; i < 2; i++)
        #pragma unroll
        for (int j = 0; j < 4; j++)
            wmma::fill_fragment(acc[i][j], 0.0f);

    const int KT = K / TILE_K;

    #pragma unroll
    for (int s = 0; s < STAGES-1; s++) {
        const float* Ab = A + (size_t)row0 * K + s * TILE_K;
        const float* Bb = B + (size_t)s * TILE_K * N + col0;
        float* Asd = As + (size_t)s * TILE_M * A_LDS;
        float* Bsd = Bs + (size_t)s * TILE_K * B_LDS;
        #pragma unroll
        for (int i = 0; i < 4; i++)
            cp_async16(Asd + (ar + i*32)*A_LDS + ac, Ab + (size_t)(ar + i*32)*K + ac);
        #pragma unroll
        for (int i = 0; i < 4; i++)
            cp_async16(Bsd + (br + i*8)*B_LDS + bc, Bb + (size_t)(br + i*8)*N + bc);
        cp_commit();
    }

    for (int kt = 0; kt < KT; kt++) {
        cp_wait<STAGES-2>();
        __syncthreads();
        int knext = kt + STAGES - 1;
        if (knext < KT) {
            int s = knext % STAGES;
            const float* Ab = A + (size_t)row0 * K + knext * TILE_K;
            const float* Bb = B + (size_t)knext * TILE_K * N + col0;
            float* Asd = As + (size_t)s * TILE_M * A_LDS;
            float* Bsd = Bs + (size_t)s * TILE_K * B_LDS;
            #pragma unroll
            for (int i = 0; i < 4; i++)
                cp_async16(Asd + (ar + i*32)*A_LDS + ac, Ab + (size_t)(ar + i*32)*K + ac);
            #pragma unroll
            for (int i = 0; i < 4; i++)
                cp_async16(Bsd + (br + i*8)*B_LDS + bc, Bb + (size_t)(br + i*8)*N + bc);
            cp_commit();
        }
        GEMM_COMPUTE_STAGE(kt % STAGES);
    }

    #pragma unroll
    for (int i = 0; i < 2; i++)
        #pragma unroll
        for (int j = 0; j < 4; j++) {
            if (ROUND_OUT) {
                #pragma unroll
                for (int t = 0; t < acc[i][j].num_elements; t++)
                    acc[i][j].x[t] = wmma::__float_to_tf32(acc[i][j].x[t]);
            }
            wmma::store_matrix_sync(&C[(size_t)(row0 + wm*32 + i*16) * N + col0 + wn*64 + j*16],
                                    acc[i][j], N, wmma::mem_row_major);
        }
}

// ---------------- reg @ V -> g_O2 (from zero), pipelined -----------------------
__global__ void __launch_bounds__(256, 2)
regv_pipe(const float* __restrict__ reg,
          const float* __restrict__ qkv,
          float* __restrict__ O2)
{
    extern __shared__ float smp[];
    float* As = smp;
    float* Bs = smp + (size_t)STAGES * TILE_M * A_LDS;

    const int h    = blockIdx.z;
    const int tid  = threadIdx.x;
    const int warp = tid >> 5;
    const int wm   = warp >> 1;
    const int wn   = warp & 1;
    const int row0 = blockIdx.y * TILE_M;
    const int col0 = blockIdx.x * TILE_N;

    const float* A = reg + (size_t)h * NTOK * NTOK;
    const int K = NTOK;

    const int ar = tid >> 3,  ac = (tid & 7)  << 2;
    const int br = tid >> 5,  bc = (tid & 31) << 2;
    const int jcol = col0 + bc;
    const int gb = jcol >> 6, gd = jcol & 63;
    const float* Vbase = qkv + (size_t)gb * (NTOK*QKV_COLS) + 2*NHEAD*HDIM + h*64 + gd;

    wmma::fragment<wmma::accumulator,16,16,8,float> acc[2][4];
    #pragma unroll
    for (int i = 0; i < 2; i++)
        #pragma unroll
        for (int j = 0; j < 4; j++)
            wmma::fill_fragment(acc[i][j], 0.0f);

    const int KT = K / TILE_K;

    #pragma unroll
    for (int s = 0; s < STAGES-1; s++) {
        const float* Abp = A + (size_t)row0 * K + s * TILE_K;
        float* Asd = As + (size_t)s * TILE_M * A_LDS;
        float* Bsd = Bs + (size_t)s * TILE_K * B_LDS;
        #pragma unroll
        for (int i = 0; i < 4; i++)
            cp_async16(Asd + (ar + i*32)*A_LDS + ac, Abp + (size_t)(ar + i*32)*K + ac);
        #pragma unroll
        for (int i = 0; i < 4; i++)
            cp_async16(Bsd + (br + i*8)*B_LDS + bc,
                       Vbase + (size_t)(s*TILE_K + br + i*8) * QKV_COLS);
        cp_commit();
    }

    for (int kt = 0; kt < KT; kt++) {
        cp_wait<STAGES-2>();
        __syncthreads();
        int knext = kt + STAGES - 1;
        if (knext < KT) {
            int s = knext % STAGES;
            const float* Abp = A + (size_t)row0 * K + knext * TILE_K;
            float* Asd = As + (size_t)s * TILE_M * A_LDS;
            float* Bsd = Bs + (size_t)s * TILE_K * B_LDS;
            #pragma unroll
            for (int i = 0; i < 4; i++)
                cp_async16(Asd + (ar + i*32)*A_LDS + ac, Abp + (size_t)(ar + i*32)*K + ac);
            #pragma unroll
            for (int i = 0; i < 4; i++)
                cp_async16(Bsd + (br + i*8)*B_LDS + bc,
                           Vbase + (size_t)(knext*TILE_K + br + i*8) * QKV_COLS);
            cp_commit();
        }
        GEMM_COMPUTE_STAGE(kt % STAGES);
    }

    #pragma unroll
    for (int i = 0; i < 2; i++)
        #pragma unroll
        for (int j = 0; j < 4; j++) {
            int rowf = row0 + wm*32 + i*16;
            int colf = col0 + wn*64 + j*16;
            int b = colf >> 6, d = colf & 63;
            float* p = O2 + (size_t)b * (NTOK*DIM) + (size_t)rowf * DIM + h*64 + d;
            wmma::store_matrix_sync(p, acc[i][j], DIM, wmma::mem_row_major);
        }
}

// ---------------- fused flash attention: 64-row Q blocks, 2 CTAs/SM -----------
// 128 threads (4 warps), Q block 64 rows, KV chunks 64 rows, K+V double-buffered.
// smem (floats): q_s [64][68] @0, k_s 2x[64][68] @4352, v_s 2x[64][68] @13056,
//                s_s [64][68] @21760 ; total 26112 floats = 104448 B -> 2 CTA/SM
#define FLASH_SMEM_BYTES 104448
#define FKBUF (64*68)   // 4352

__global__ void __launch_bounds__(128, 2)
flash_kernel(const float* __restrict__ qkv, float* __restrict__ O)
{
    extern __shared__ float sm[];
    float* q_s = sm;
    float* k_s = sm + 4352;
    float* v_s = sm + 13056;
    float* s_s = sm + 21760;

    const int qb   = blockIdx.x;      // 64-row q block
    const int h    = blockIdx.y;
    const int b    = blockIdx.z;
    const int tid  = threadIdx.x;
    const int warp = tid >> 5;

    const size_t bhbase = (size_t)(b*NTOK) * QKV_COLS + h*64;

    // prologue: chunk 0 (K and V), one commit group
    {
        const float* kb = qkv + bhbase + NHEAD*HDIM;
        const float* vb = qkv + bhbase + 2*NHEAD*HDIM;
        #pragma unroll
        for (int i = 0; i < 8; i++) {
            int idx = tid + i * 128;                 // 1024 float4 each
            int r = idx >> 4, c = (idx & 15) << 2;
            cp_async16(&k_s[r*68 + c], kb + (size_t)r * QKV_COLS + c);
            cp_async16(&v_s[r*68 + c], vb + (size_t)r * QKV_COLS + c);
        }
        cp_commit();
    }

    // load Q (pre-scaled) while chunk 0 is in flight
    const size_t qbase = bhbase + (size_t)(qb*64) * QKV_COLS;
    #pragma unroll
    for (int i = 0; i < 8; i++) {
        int idx = tid + i * 128;                     // 1024 float4
        int r = idx >> 4, c = (idx & 15) << 2;
        float4 v = *reinterpret_cast<const float4*>(&qkv[qbase + (size_t)r * QKV_COLS + c]);
        q_s[r*68 + c    ] = v.x * SCALE;
        q_s[r*68 + c + 1] = v.y * SCALE;
        q_s[r*68 + c + 2] = v.z * SCALE;
        q_s[r*68 + c + 3] = v.w * SCALE;
    }

    const int srow = tid >> 1;                       // owned row 0..63
    const int half = tid & 1;
    float o_reg[32];
    #pragma unroll
    for (int c = 0; c < 32; c++) o_reg[c] = 0.0f;
    float m_run = -1e30f, l_run = 0.0f;

    for (int j = 0; j < 16; j++) {
        cp_wait<0>();            // chunk j resident
        __syncthreads();         // + all warps done with buffer (j+1)&1 (iter j-1)

        if (j < 15) {            // prefetch chunk j+1 into the other buffer
            const float* kb = qkv + bhbase + (size_t)((j+1)*64) * QKV_COLS + NHEAD*HDIM;
            const float* vb = qkv + bhbase + (size_t)((j+1)*64) * QKV_COLS + 2*NHEAD*HDIM;
            float* kd = k_s + ((j+1) & 1) * FKBUF;
            float* vd = v_s + ((j+1) & 1) * FKBUF;
            #pragma unroll
            for (int i = 0; i < 8; i++) {
                int idx = tid + i * 128;
                int r = idx >> 4, c = (idx & 15) << 2;
                cp_async16(&kd[r*68 + c], kb + (size_t)r * QKV_COLS + c);
                cp_async16(&vd[r*68 + c], vb + (size_t)r * QKV_COLS + c);
            }
            cp_commit();
        }

        const float* kcur = k_s + (j & 1) * FKBUF;
        const float* vcur = v_s + (j & 1) * FKBUF;

        // ---- S = Qs @ K^T : warp w -> 16 rows x 64 cols
        {
            wmma::fragment<wmma::accumulator,16,16,8,float> sacc[4];
            #pragma unroll
            for (int n = 0; n < 4; n++) wmma::fill_fragment(sacc[n], 0.0f);
            #pragma unroll
            for (int kk = 0; kk < 64; kk += 8) {
                wmma::fragment<wmma::matrix_a,16,16,8,wmma::precision::tf32,wmma::row_major> af;
                wmma::load_matrix_sync(af, &q_s[(warp*16)*68 + kk], 68);
                #pragma unroll
                for (int n = 0; n < 4; n++) {
                    wmma::fragment<wmma::matrix_b,16,16,8,wmma::precision::tf32,wmma::col_major> bf;
                    wmma::load_matrix_sync(bf, &kcur[(n*16)*68 + kk], 68);
                    wmma::mma_sync(sacc[n], af, bf, sacc[n]);
                }
            }
            #pragma unroll
            for (int n = 0; n < 4; n++)
                wmma::store_matrix_sync(&s_s[(warp*16)*68 + n*16], sacc[n], 68, wmma::mem_row_major);
        }
        __syncwarp();

        // ---- online softmax: 2 threads/row, 32 cols each
        {
            float* sp = &s_s[srow*68 + half*32];
            float mx = -1e30f;
            #pragma unroll
            for (int c = 0; c < 32; c++) mx = fmaxf(mx, sp[c]);
            mx = fmaxf(mx, __shfl_xor_sync(0xffffffffu, mx, 1));
            float m_new = fmaxf(m_run, mx);
            float corr  = __expf(m_run - m_new);
            float sum = 0.0f;
            #pragma unroll
            for (int c = 0; c < 32; c++) {
                float p = wmma::__float_to_tf32(__expf(sp[c] - m_new));
                sp[c] = p;
                sum += p;
            }
            sum += __shfl_xor_sync(0xffffffffu, sum, 1);
            l_run = l_run * corr + sum;
            m_run = m_new;
            #pragma unroll
            for (int c = 0; c < 32; c++) o_reg[c] *= corr;
        }
        __syncwarp();

        // ---- PV: own 16 rows of P[64x64] @ V[64x64] -> stash over s_s rows
        {
            wmma::fragment<wmma::accumulator,16,16,8,float> oacc[4];
            #pragma unroll
            for (int n = 0; n < 4; n++) wmma::fill_fragment(oacc[n], 0.0f);
            #pragma unroll
            for (int kk = 0; kk < 64; kk += 8) {
                wmma::fragment<wmma::matrix_a,16,16,8,wmma::precision::tf32,wmma::row_major> af;
                wmma::load_matrix_sync(af, &s_s[(warp*16)*68 + kk], 68);
                #pragma unroll
                for (int n = 0; n < 4; n++) {
                    wmma::fragment<wmma::matrix_b,16,16,8,wmma::precision::tf32,wmma::row_major> bf;
                    wmma::load_matrix_sync(bf, &vcur[kk*68 + n*16], 68);
                    wmma::mma_sync(oacc[n], af, bf, oacc[n]);
                }
            }
            #pragma unroll
            for (int n = 0; n < 4; n++)
                wmma::store_matrix_sync(&s_s[(warp*16)*68 + n*16], oacc[n], 68, wmma::mem_row_major);
        }
        __syncwarp();
        #pragma unroll
        for (int c = 0; c < 32; c++)
            o_reg[c] += s_s[srow*68 + half*32 + c];
        // barrier at top of next iteration protects buffers/s_s
    }

    // epilogue from registers
    float inv_l = 1.0f / l_run;
    float* op = O + (size_t)(b*NTOK + qb*64 + srow) * DIM + h*64 + half*32;
    #pragma unroll
    for (int c = 0; c < 32; c += 4) {
        float4 v;
        v.x = o_reg[c    ] * inv_l;
        v.y = o_reg[c + 1] * inv_l;
        v.z = o_reg[c + 2] * inv_l;
        v.w = o_reg[c + 3] * inv_l;
        *reinterpret_cast<float4*>(op + c) = v;
    }
}

// ---------------- bias add ----------------------------------------------------
__global__ void bias_add_kernel(float* __restrict__ out, const float* __restrict__ bias)
{
    int i = blockIdx.x * blockDim.x + threadIdx.x;
    const int n4 = (BATCH*NTOK*DIM) / 4;
    if (i < n4) {
        float4 o = reinterpret_cast<float4*>(out)[i];
        float4 bv = reinterpret_cast<const float4*>(bias)[i & 255];
        o.x += bv.x; o.y += bv.y; o.z += bv.z; o.w += bv.w;
        reinterpret_cast<float4*>(out)[i] = o;
    }
}

// ---------------- launcher ----------------------------------------------------
extern "C" void kernel_launch(void* const* d_in, const int* in_sizes, int n_in,
                              void* d_out, int out_size)
{
    const float* x      = (const float*)d_in[0];
    const float* W_qkv  = (const float*)d_in[1];
    const float* reg    = (const float*)d_in[2];
    const float* W_proj = (const float*)d_in[3];
    const float* b_proj = (const float*)d_in[4];
    float* out = (float*)d_out;

    float *qkv_ptr, *O_ptr, *O2_ptr, *xr, *wqkvr, *wpr, *regr;
    cudaGetSymbolAddress((void**)&qkv_ptr, g_qkv);
    cudaGetSymbolAddress((void**)&O_ptr,   g_O);
    cudaGetSymbolAddress((void**)&O2_ptr,  g_O2);
    cudaGetSymbolAddress((void**)&xr,      g_xr);
    cudaGetSymbolAddress((void**)&wqkvr,   g_wqkvr);
    cudaGetSymbolAddress((void**)&wpr,     g_wpr);
    cudaGetSymbolAddress((void**)&regr,    g_regr);

    cudaFuncSetAttribute(gemm_tf32_pipe<true>,  cudaFuncAttributeMaxDynamicSharedMemorySize, GEMM_SMEM_BYTES);
    cudaFuncSetAttribute(gemm_tf32_pipe<false>, cudaFuncAttributeMaxDynamicSharedMemorySize, GEMM_SMEM_BYTES);
    cudaFuncSetAttribute(regv_pipe,             cudaFuncAttributeMaxDynamicSharedMemorySize, GEMM_SMEM_BYTES);
    cudaFuncSetAttribute(flash_kernel,          cudaFuncAttributeMaxDynamicSharedMemorySize, FLASH_SMEM_BYTES);

    // side stream + fork/join events (created once; reused — work per call identical)
    static cudaStream_t s2 = nullptr;
    static cudaEvent_t evFork = nullptr, evQKV = nullptr, evRegv = nullptr;
    if (!s2) {
        cudaStreamCreateWithFlags(&s2, cudaStreamNonBlocking);
        cudaEventCreateWithFlags(&evFork, cudaEventDisableTiming);
        cudaEventCreateWithFlags(&evQKV,  cudaEventDisableTiming);
        cudaEventCreateWithFlags(&evRegv, cudaEventDisableTiming);
    }

    // ---- main: round x, W_qkv (QKV deps) ----
    {
        int n4;
        n4 = (BATCH*NTOK*DIM)/4;  round_tf32_kernel<<<(n4+255)/256, 256>>>(x, xr, n4);
        n4 = (DIM*QKV_COLS)/4;    round_tf32_kernel<<<(n4+255)/256, 256>>>(W_qkv, wqkvr, n4);
    }
    cudaEventRecord(evFork, 0);

    // ---- side: round W_proj + reg (overlaps QKV GEMM) ----
    cudaStreamWaitEvent(s2, evFork, 0);
    {
        int n4;
        n4 = (DIM*DIM)/4;          round_tf32_kernel<<<(n4+255)/256, 256, 0, s2>>>(W_proj, wpr, n4);
        n4 = (NHEAD*NTOK*NTOK)/4;  round_tf32_kernel<<<(n4+255)/256, 256, 0, s2>>>(reg, regr, n4);
    }

    // ---- main: QKV projection ----
    {
        dim3 grid(QKV_COLS / TILE_N, (BATCH*NTOK) / TILE_M);
        gemm_tf32_pipe<true><<<grid, 256, GEMM_SMEM_BYTES>>>(xr, wqkvr, qkv_ptr,
                                                             BATCH*NTOK, QKV_COLS, DIM);
    }
    cudaEventRecord(evQKV, 0);

    // ---- side: regv (needs qkv + regr) ----
    cudaStreamWaitEvent(s2, evQKV, 0);
    {
        dim3 grid((BATCH*HDIM) / TILE_N, NTOK / TILE_M, NHEAD);
        regv_pipe<<<grid, 256, GEMM_SMEM_BYTES, s2>>>(regr, qkv_ptr, O2_ptr);
    }
    cudaEventRecord(evRegv, s2);

    // ---- main: flash attention -> g_O (64-row blocks, 2 CTAs/SM) ----
    {
        dim3 grid(NTOK / 64, NHEAD, BATCH);
        flash_kernel<<<grid, 128, FLASH_SMEM_BYTES>>>(qkv_ptr, O_ptr);
    }

    // ---- join: merge O += O2 (rounded), then proj ----
    cudaStreamWaitEvent(0, evRegv, 0);
    {
        int n4 = (BATCH*NTOK*DIM)/4;
        merge_round_kernel<<<(n4+255)/256, 256>>>(O_ptr, O2_ptr, n4);
    }
    {
        dim3 grid(DIM / TILE_N, (BATCH*NTOK) / TILE_M);
        gemm_tf32_pipe<false><<<grid, 256, GEMM_SMEM_BYTES>>>(O_ptr, wpr, out,
                                                              BATCH*NTOK, DIM, DIM);
    }
    {
        int n4 = (BATCH*NTOK*DIM) / 4;
        bias_add_kernel<<<(n4 + 255) / 256, 256>>>(out, b_proj);
    }
}

// round 12
// speedup vs baseline: 1.2805x; 1.0478x over previous
#include <cuda_runtime.h>
#include <cuda_bf16.h>
#include <mma.h>
#include <math.h>
#include <cstdint>

using namespace nvcuda;

// Problem constants
#define BATCH 8
#define NTOK  1024
#define DIM   1024
#define NHEAD 16
#define HDIM  64
#define QKV_COLS (3*NHEAD*HDIM)   // 3072
#define SCALE 0.125f              // 64^-0.5

// ---------------- scratch (device globals: no allocations allowed) -----------
__device__ float g_qkv [(size_t)BATCH*NTOK*QKV_COLS];
__device__ float g_O   [(size_t)BATCH*NTOK*DIM];      // flash output
__device__ float g_O2  [(size_t)BATCH*NTOK*DIM];      // regv output
__device__ float g_xr  [(size_t)BATCH*NTOK*DIM];
__device__ float g_wqkvr[(size_t)DIM*QKV_COLS];
__device__ float g_wpr [(size_t)DIM*DIM];
__device__ float g_regr[(size_t)NHEAD*NTOK*NTOK];

// ---------------- cp.async helpers -------------------------------------------
__device__ __forceinline__ void cp_async16(float* smem, const float* gmem) {
    unsigned int s = (unsigned int)__cvta_generic_to_shared(smem);
    asm volatile("cp.async.cg.shared.global [%0], [%1], 16;\n" :: "r"(s), "l"(gmem));
}
__device__ __forceinline__ void cp_commit() {
    asm volatile("cp.async.commit_group;\n" ::: "memory");
}
template<int N>
__device__ __forceinline__ void cp_wait() {
    asm volatile("cp.async.wait_group %0;\n" :: "n"(N) : "memory");
}

// ---------------- elementwise tf32 rounding ----------------------------------
__global__ void round_tf32_kernel(const float* __restrict__ in,
                                  float* __restrict__ out, int n4)
{
    int i = blockIdx.x * blockDim.x + threadIdx.x;
    if (i < n4) {
        float4 v = reinterpret_cast<const float4*>(in)[i];
        v.x = wmma::__float_to_tf32(v.x);
        v.y = wmma::__float_to_tf32(v.y);
        v.z = wmma::__float_to_tf32(v.z);
        v.w = wmma::__float_to_tf32(v.w);
        reinterpret_cast<float4*>(out)[i] = v;
    }
}

// ---------------- merge: O = round_tf32(O + O2) --------------------------------
__global__ void merge_round_kernel(float* __restrict__ o,
                                   const float* __restrict__ o2, int n4)
{
    int i = blockIdx.x * blockDim.x + threadIdx.x;
    if (i < n4) {
        float4 a = reinterpret_cast<float4*>(o)[i];
        float4 b = reinterpret_cast<const float4*>(o2)[i];
        a.x = wmma::__float_to_tf32(a.x + b.x);
        a.y = wmma::__float_to_tf32(a.y + b.y);
        a.z = wmma::__float_to_tf32(a.z + b.z);
        a.w = wmma::__float_to_tf32(a.w + b.w);
        reinterpret_cast<float4*>(o)[i] = a;
    }
}

// ---------------- pipelined tf32 GEMM: C[M,N] = A[M,K] @ B[K,N] ---------------
// 128 threads = 4 warps (2x2), warp tile 64x64 (4x4 fragments) -> mma/frag-load
// ratio 2.0 (was 1.33). CTA tile 128x128, K-tile 32, 3-stage cp.async, 2 CTA/SM.
#define TILE_M 128
#define TILE_N 128
#define TILE_K 32
#define STAGES 3
#define A_LDS 40
#define B_LDS 136
#define GEMM_SMEM_BYTES (STAGES * (TILE_M*A_LDS + TILE_K*B_LDS) * 4)  // 113664

// compute over one resident stage: warp (wm,wn) owns rows wm*64..+64, cols wn*64..+64
#define GEMM_COMPUTE_STAGE(sidx)                                                   \
    {                                                                              \
        const float* Asb = As + (size_t)(sidx) * TILE_M * A_LDS;                   \
        const float* Bsb = Bs + (size_t)(sidx) * TILE_K * B_LDS;                   \
        _Pragma("unroll")                                                          \
        for (int kk = 0; kk < TILE_K; kk += 8) {                                   \
            wmma::fragment<wmma::matrix_a,16,16,8,wmma::precision::tf32,wmma::row_major> af[4]; \
            wmma::fragment<wmma::matrix_b,16,16,8,wmma::precision::tf32,wmma::row_major> bf[4]; \
            _Pragma("unroll")                                                      \
            for (int i = 0; i < 4; i++)                                            \
                wmma::load_matrix_sync(af[i], Asb + (wm*64 + i*16)*A_LDS + kk, A_LDS); \
            _Pragma("unroll")                                                      \
            for (int j = 0; j < 4; j++)                                            \
                wmma::load_matrix_sync(bf[j], Bsb + kk*B_LDS + wn*64 + j*16, B_LDS); \
            _Pragma("unroll")                                                      \
            for (int i = 0; i < 4; i++)                                            \
                _Pragma("unroll")                                                  \
                for (int j = 0; j < 4; j++)                                        \
                    wmma::mma_sync(acc[i][j], af[i], bf[j], acc[i][j]);            \
        }                                                                          \
    }

// per-thread cp.async of one stage (128 threads)
#define GEMM_LOAD_STAGE(sidx, ktile)                                               \
    {                                                                              \
        const float* Ab = A + (size_t)row0 * K + (ktile) * TILE_K;                 \
        const float* Bb = B + (size_t)(ktile) * TILE_K * N + col0;                 \
        float* Asd = As + (size_t)(sidx) * TILE_M * A_LDS;                         \
        float* Bsd = Bs + (size_t)(sidx) * TILE_K * B_LDS;                         \
        _Pragma("unroll")                                                          \
        for (int i = 0; i < 8; i++) {                                              \
            int idx = tid + i * 128;                                               \
            int r = idx >> 3, c = (idx & 7) << 2;                                  \
            cp_async16(Asd + r*A_LDS + c, Ab + (size_t)r * K + c);                 \
        }                                                                          \
        _Pragma("unroll")                                                          \
        for (int i = 0; i < 8; i++) {                                              \
            int idx = tid + i * 128;                                               \
            int r = idx >> 5, c = (idx & 31) << 2;                                 \
            cp_async16(Bsd + r*B_LDS + c, Bb + (size_t)r * N + c);                 \
        }                                                                          \
        cp_commit();                                                               \
    }

template<bool ROUND_OUT>
__global__ void __launch_bounds__(128, 2)
gemm_tf32_pipe(const float* __restrict__ A,
               const float* __restrict__ B,
               float* __restrict__ C,
               int M, int N, int K)
{
    extern __shared__ float smp[];
    float* As = smp;
    float* Bs = smp + (size_t)STAGES * TILE_M * A_LDS;

    const int tid  = threadIdx.x;
    const int warp = tid >> 5;
    const int wm   = warp >> 1;    // 0..1 -> 64 rows
    const int wn   = warp & 1;     // 0..1 -> 64 cols
    const int row0 = blockIdx.y * TILE_M;
    const int col0 = blockIdx.x * TILE_N;

    wmma::fragment<wmma::accumulator,16,16,8,float> acc[4][4];
    #pragma unroll
    for (int i = 0; i < 4; i++)
        #pragma unroll
        for (int j = 0; j < 4; j++)
            wmma::fill_fragment(acc[i][j], 0.0f);

    const int KT = K / TILE_K;

    #pragma unroll
    for (int s = 0; s < STAGES-1; s++)
        GEMM_LOAD_STAGE(s, s)

    for (int kt = 0; kt < KT; kt++) {
        cp_wait<STAGES-2>();
        __syncthreads();
        int knext = kt + STAGES - 1;
        if (knext < KT)
            GEMM_LOAD_STAGE(knext % STAGES, knext)
        GEMM_COMPUTE_STAGE(kt % STAGES);
    }

    #pragma unroll
    for (int i = 0; i < 4; i++)
        #pragma unroll
        for (int j = 0; j < 4; j++) {
            if (ROUND_OUT) {
                #pragma unroll
                for (int t = 0; t < acc[i][j].num_elements; t++)
                    acc[i][j].x[t] = wmma::__float_to_tf32(acc[i][j].x[t]);
            }
            wmma::store_matrix_sync(&C[(size_t)(row0 + wm*64 + i*16) * N + col0 + wn*64 + j*16],
                                    acc[i][j], N, wmma::mem_row_major);
        }
}

// ---------------- reg @ V -> g_O2 (from zero), pipelined -----------------------
__global__ void __launch_bounds__(128, 2)
regv_pipe(const float* __restrict__ reg,
          const float* __restrict__ qkv,
          float* __restrict__ O2)
{
    extern __shared__ float smp[];
    float* As = smp;
    float* Bs = smp + (size_t)STAGES * TILE_M * A_LDS;

    const int h    = blockIdx.z;
    const int tid  = threadIdx.x;
    const int warp = tid >> 5;
    const int wm   = warp >> 1;
    const int wn   = warp & 1;
    const int row0 = blockIdx.y * TILE_M;
    const int col0 = blockIdx.x * TILE_N;

    const float* A = reg + (size_t)h * NTOK * NTOK;
    const int K = NTOK;

    // B gather coords: column j = col0 + bc (constant per thread), row = k
    const int bc = (tid & 31) << 2;
    const int jcol = col0 + bc;
    const int gb = jcol >> 6, gd = jcol & 63;
    const float* Vbase = qkv + (size_t)gb * (NTOK*QKV_COLS) + 2*NHEAD*HDIM + h*64 + gd;

    wmma::fragment<wmma::accumulator,16,16,8,float> acc[4][4];
    #pragma unroll
    for (int i = 0; i < 4; i++)
        #pragma unroll
        for (int j = 0; j < 4; j++)
            wmma::fill_fragment(acc[i][j], 0.0f);

    const int KT = K / TILE_K;

    #pragma unroll
    for (int s = 0; s < STAGES-1; s++) {
        const float* Abp = A + (size_t)row0 * K + s * TILE_K;
        float* Asd = As + (size_t)s * TILE_M * A_LDS;
        float* Bsd = Bs + (size_t)s * TILE_K * B_LDS;
        #pragma unroll
        for (int i = 0; i < 8; i++) {
            int idx = tid + i * 128;
            int r = idx >> 3, c = (idx & 7) << 2;
            cp_async16(Asd + r*A_LDS + c, Abp + (size_t)r * K + c);
        }
        #pragma unroll
        for (int i = 0; i < 8; i++) {
            int idx = tid + i * 128;
            int r = idx >> 5;
            cp_async16(Bsd + r*B_LDS + bc,
                       Vbase + (size_t)(s*TILE_K + r) * QKV_COLS);
        }
        cp_commit();
    }

    for (int kt = 0; kt < KT; kt++) {
        cp_wait<STAGES-2>();
        __syncthreads();
        int knext = kt + STAGES - 1;
        if (knext < KT) {
            int s = knext % STAGES;
            const float* Abp = A + (size_t)row0 * K + knext * TILE_K;
            float* Asd = As + (size_t)s * TILE_M * A_LDS;
            float* Bsd = Bs + (size_t)s * TILE_K * B_LDS;
            #pragma unroll
            for (int i = 0; i < 8; i++) {
                int idx = tid + i * 128;
                int r = idx >> 3, c = (idx & 7) << 2;
                cp_async16(Asd + r*A_LDS + c, Abp + (size_t)r * K + c);
            }
            #pragma unroll
            for (int i = 0; i < 8; i++) {
                int idx = tid + i * 128;
                int r = idx >> 5;
                cp_async16(Bsd + r*B_LDS + bc,
                           Vbase + (size_t)(knext*TILE_K + r) * QKV_COLS);
            }
            cp_commit();
        }
        GEMM_COMPUTE_STAGE(kt % STAGES);
    }

    #pragma unroll
    for (int i = 0; i < 4; i++)
        #pragma unroll
        for (int j = 0; j < 4; j++) {
            int rowf = row0 + wm*64 + i*16;
            int colf = col0 + wn*64 + j*16;
            int b = colf >> 6, d = colf & 63;
            float* p = O2 + (size_t)b * (NTOK*DIM) + (size_t)rowf * DIM + h*64 + d;
            wmma::store_matrix_sync(p, acc[i][j], DIM, wmma::mem_row_major);
        }
}

// ---------------- fused flash attention: 64-row Q blocks, 2 CTAs/SM -----------
#define FLASH_SMEM_BYTES 104448
#define FKBUF (64*68)   // 4352

__global__ void __launch_bounds__(128, 2)
flash_kernel(const float* __restrict__ qkv, float* __restrict__ O)
{
    extern __shared__ float sm[];
    float* q_s = sm;
    float* k_s = sm + 4352;
    float* v_s = sm + 13056;
    float* s_s = sm + 21760;

    const int qb   = blockIdx.x;
    const int h    = blockIdx.y;
    const int b    = blockIdx.z;
    const int tid  = threadIdx.x;
    const int warp = tid >> 5;

    const size_t bhbase = (size_t)(b*NTOK) * QKV_COLS + h*64;

    {
        const float* kb = qkv + bhbase + NHEAD*HDIM;
        const float* vb = qkv + bhbase + 2*NHEAD*HDIM;
        #pragma unroll
        for (int i = 0; i < 8; i++) {
            int idx = tid + i * 128;
            int r = idx >> 4, c = (idx & 15) << 2;
            cp_async16(&k_s[r*68 + c], kb + (size_t)r * QKV_COLS + c);
            cp_async16(&v_s[r*68 + c], vb + (size_t)r * QKV_COLS + c);
        }
        cp_commit();
    }

    const size_t qbase = bhbase + (size_t)(qb*64) * QKV_COLS;
    #pragma unroll
    for (int i = 0; i < 8; i++) {
        int idx = tid + i * 128;
        int r = idx >> 4, c = (idx & 15) << 2;
        float4 v = *reinterpret_cast<const float4*>(&qkv[qbase + (size_t)r * QKV_COLS + c]);
        q_s[r*68 + c    ] = v.x * SCALE;
        q_s[r*68 + c + 1] = v.y * SCALE;
        q_s[r*68 + c + 2] = v.z * SCALE;
        q_s[r*68 + c + 3] = v.w * SCALE;
    }

    const int srow = tid >> 1;
    const int half = tid & 1;
    float o_reg[32];
    #pragma unroll
    for (int c = 0; c < 32; c++) o_reg[c] = 0.0f;
    float m_run = -1e30f, l_run = 0.0f;

    for (int j = 0; j < 16; j++) {
        cp_wait<0>();
        __syncthreads();

        if (j < 15) {
            const float* kb = qkv + bhbase + (size_t)((j+1)*64) * QKV_COLS + NHEAD*HDIM;
            const float* vb = qkv + bhbase + (size_t)((j+1)*64) * QKV_COLS + 2*NHEAD*HDIM;
            float* kd = k_s + ((j+1) & 1) * FKBUF;
            float* vd = v_s + ((j+1) & 1) * FKBUF;
            #pragma unroll
            for (int i = 0; i < 8; i++) {
                int idx = tid + i * 128;
                int r = idx >> 4, c = (idx & 15) << 2;
                cp_async16(&kd[r*68 + c], kb + (size_t)r * QKV_COLS + c);
                cp_async16(&vd[r*68 + c], vb + (size_t)r * QKV_COLS + c);
            }
            cp_commit();
        }

        const float* kcur = k_s + (j & 1) * FKBUF;
        const float* vcur = v_s + (j & 1) * FKBUF;

        {
            wmma::fragment<wmma::accumulator,16,16,8,float> sacc[4];
            #pragma unroll
            for (int n = 0; n < 4; n++) wmma::fill_fragment(sacc[n], 0.0f);
            #pragma unroll
            for (int kk = 0; kk < 64; kk += 8) {
                wmma::fragment<wmma::matrix_a,16,16,8,wmma::precision::tf32,wmma::row_major> af;
                wmma::load_matrix_sync(af, &q_s[(warp*16)*68 + kk], 68);
                #pragma unroll
                for (int n = 0; n < 4; n++) {
                    wmma::fragment<wmma::matrix_b,16,16,8,wmma::precision::tf32,wmma::col_major> bf;
                    wmma::load_matrix_sync(bf, &kcur[(n*16)*68 + kk], 68);
                    wmma::mma_sync(sacc[n], af, bf, sacc[n]);
                }
            }
            #pragma unroll
            for (int n = 0; n < 4; n++)
                wmma::store_matrix_sync(&s_s[(warp*16)*68 + n*16], sacc[n], 68, wmma::mem_row_major);
        }
        __syncwarp();

        {
            float* sp = &s_s[srow*68 + half*32];
            float mx = -1e30f;
            #pragma unroll
            for (int c = 0; c < 32; c++) mx = fmaxf(mx, sp[c]);
            mx = fmaxf(mx, __shfl_xor_sync(0xffffffffu, mx, 1));
            float m_new = fmaxf(m_run, mx);
            float corr  = __expf(m_run - m_new);
            float sum = 0.0f;
            #pragma unroll
            for (int c = 0; c < 32; c++) {
                float p = wmma::__float_to_tf32(__expf(sp[c] - m_new));
                sp[c] = p;
                sum += p;
            }
            sum += __shfl_xor_sync(0xffffffffu, sum, 1);
            l_run = l_run * corr + sum;
            m_run = m_new;
            #pragma unroll
            for (int c = 0; c < 32; c++) o_reg[c] *= corr;
        }
        __syncwarp();

        {
            wmma::fragment<wmma::accumulator,16,16,8,float> oacc[4];
            #pragma unroll
            for (int n = 0; n < 4; n++) wmma::fill_fragment(oacc[n], 0.0f);
            #pragma unroll
            for (int kk = 0; kk < 64; kk += 8) {
                wmma::fragment<wmma::matrix_a,16,16,8,wmma::precision::tf32,wmma::row_major> af;
                wmma::load_matrix_sync(af, &s_s[(warp*16)*68 + kk], 68);
                #pragma unroll
                for (int n = 0; n < 4; n++) {
                    wmma::fragment<wmma::matrix_b,16,16,8,wmma::precision::tf32,wmma::row_major> bf;
                    wmma::load_matrix_sync(bf, &vcur[kk*68 + n*16], 68);
                    wmma::mma_sync(oacc[n], af, bf, oacc[n]);
                }
            }
            #pragma unroll
            for (int n = 0; n < 4; n++)
                wmma::store_matrix_sync(&s_s[(warp*16)*68 + n*16], oacc[n], 68, wmma::mem_row_major);
        }
        __syncwarp();
        #pragma unroll
        for (int c = 0; c < 32; c++)
            o_reg[c] += s_s[srow*68 + half*32 + c];
    }

    float inv_l = 1.0f / l_run;
    float* op = O + (size_t)(b*NTOK + qb*64 + srow) * DIM + h*64 + half*32;
    #pragma unroll
    for (int c = 0; c < 32; c += 4) {
        float4 v;
        v.x = o_reg[c    ] * inv_l;
        v.y = o_reg[c + 1] * inv_l;
        v.z = o_reg[c + 2] * inv_l;
        v.w = o_reg[c + 3] * inv_l;
        *reinterpret_cast<float4*>(op + c) = v;
    }
}

// ---------------- bias add ----------------------------------------------------
__global__ void bias_add_kernel(float* __restrict__ out, const float* __restrict__ bias)
{
    int i = blockIdx.x * blockDim.x + threadIdx.x;
    const int n4 = (BATCH*NTOK*DIM) / 4;
    if (i < n4) {
        float4 o = reinterpret_cast<float4*>(out)[i];
        float4 bv = reinterpret_cast<const float4*>(bias)[i & 255];
        o.x += bv.x; o.y += bv.y; o.z += bv.z; o.w += bv.w;
        reinterpret_cast<float4*>(out)[i] = o;
    }
}

// ---------------- launcher ----------------------------------------------------
extern "C" void kernel_launch(void* const* d_in, const int* in_sizes, int n_in,
                              void* d_out, int out_size)
{
    const float* x      = (const float*)d_in[0];
    const float* W_qkv  = (const float*)d_in[1];
    const float* reg    = (const float*)d_in[2];
    const float* W_proj = (const float*)d_in[3];
    const float* b_proj = (const float*)d_in[4];
    float* out = (float*)d_out;

    float *qkv_ptr, *O_ptr, *O2_ptr, *xr, *wqkvr, *wpr, *regr;
    cudaGetSymbolAddress((void**)&qkv_ptr, g_qkv);
    cudaGetSymbolAddress((void**)&O_ptr,   g_O);
    cudaGetSymbolAddress((void**)&O2_ptr,  g_O2);
    cudaGetSymbolAddress((void**)&xr,      g_xr);
    cudaGetSymbolAddress((void**)&wqkvr,   g_wqkvr);
    cudaGetSymbolAddress((void**)&wpr,     g_wpr);
    cudaGetSymbolAddress((void**)&regr,    g_regr);

    cudaFuncSetAttribute(gemm_tf32_pipe<true>,  cudaFuncAttributeMaxDynamicSharedMemorySize, GEMM_SMEM_BYTES);
    cudaFuncSetAttribute(gemm_tf32_pipe<false>, cudaFuncAttributeMaxDynamicSharedMemorySize, GEMM_SMEM_BYTES);
    cudaFuncSetAttribute(regv_pipe,             cudaFuncAttributeMaxDynamicSharedMemorySize, GEMM_SMEM_BYTES);
    cudaFuncSetAttribute(flash_kernel,          cudaFuncAttributeMaxDynamicSharedMemorySize, FLASH_SMEM_BYTES);

    static cudaStream_t s2 = nullptr;
    static cudaEvent_t evFork = nullptr, evQKV = nullptr, evRegv = nullptr;
    if (!s2) {
        cudaStreamCreateWithFlags(&s2, cudaStreamNonBlocking);
        cudaEventCreateWithFlags(&evFork, cudaEventDisableTiming);
        cudaEventCreateWithFlags(&evQKV,  cudaEventDisableTiming);
        cudaEventCreateWithFlags(&evRegv, cudaEventDisableTiming);
    }

    // ---- main: round x, W_qkv ----
    {
        int n4;
        n4 = (BATCH*NTOK*DIM)/4;  round_tf32_kernel<<<(n4+255)/256, 256>>>(x, xr, n4);
        n4 = (DIM*QKV_COLS)/4;    round_tf32_kernel<<<(n4+255)/256, 256>>>(W_qkv, wqkvr, n4);
    }
    cudaEventRecord(evFork, 0);

    // ---- side: round W_proj + reg (overlaps QKV GEMM) ----
    cudaStreamWaitEvent(s2, evFork, 0);
    {
        int n4;
        n4 = (DIM*DIM)/4;          round_tf32_kernel<<<(n4+255)/256, 256, 0, s2>>>(W_proj, wpr, n4);
        n4 = (NHEAD*NTOK*NTOK)/4;  round_tf32_kernel<<<(n4+255)/256, 256, 0, s2>>>(reg, regr, n4);
    }

    // ---- main: QKV projection ----
    {
        dim3 grid(QKV_COLS / TILE_N, (BATCH*NTOK) / TILE_M);
        gemm_tf32_pipe<true><<<grid, 128, GEMM_SMEM_BYTES>>>(xr, wqkvr, qkv_ptr,
                                                             BATCH*NTOK, QKV_COLS, DIM);
    }
    cudaEventRecord(evQKV, 0);

    // ---- side: regv ----
    cudaStreamWaitEvent(s2, evQKV, 0);
    {
        dim3 grid((BATCH*HDIM) / TILE_N, NTOK / TILE_M, NHEAD);
        regv_pipe<<<grid, 128, GEMM_SMEM_BYTES, s2>>>(regr, qkv_ptr, O2_ptr);
    }
    cudaEventRecord(evRegv, s2);

    // ---- main: flash attention -> g_O ----
    {
        dim3 grid(NTOK / 64, NHEAD, BATCH);
        flash_kernel<<<grid, 128, FLASH_SMEM_BYTES>>>(qkv_ptr, O_ptr);
    }

    // ---- join: merge, proj, bias ----
    cudaStreamWaitEvent(0, evRegv, 0);
    {
        int n4 = (BATCH*NTOK*DIM)/4;
        merge_round_kernel<<<(n4+255)/256, 256>>>(O_ptr, O2_ptr, n4);
    }
    {
        dim3 grid(DIM / TILE_N, (BATCH*NTOK) / TILE_M);
        gemm_tf32_pipe<false><<<grid, 128, GEMM_SMEM_BYTES>>>(O_ptr, wpr, out,
                                                              BATCH*NTOK, DIM, DIM);
    }
    {
        int n4 = (BATCH*NTOK*DIM) / 4;
        bias_add_kernel<<<(n4 + 255) / 256, 256>>>(out, b_proj);
    }
}